// round 4
// baseline (speedup 1.0000x reference)
#include <cuda_runtime.h>
#include <math.h>

#define HH 128
#define WW 128
#define HW (HH * WW)
#define BB 2

typedef unsigned long long u64;

// ---------------- scratch (static device allocations; no runtime alloc) ----
__device__ float g_feat1[BB * 64 * HW];    // after conv1+lrelu
__device__ float g_feat2[BB * 64 * HW];    // after conv2+lrelu
__device__ float g_om[BB * 216 * HW];      // raw conv_om output
__device__ float g_dcnw[8 * 9 * 8 * 64];   // repacked dcn weights [(g*9+k)][c][o]

// ---------------- packed f32x2 helpers (FFMA2 path, sm_100+) ---------------
__device__ __forceinline__ u64 pk2(float lo, float hi) {
    u64 r; asm("mov.b64 %0, {%1, %2};" : "=l"(r) : "f"(lo), "f"(hi)); return r;
}
__device__ __forceinline__ void upk2(u64 v, float& lo, float& hi) {
    asm("mov.b64 {%0, %1}, %2;" : "=f"(lo), "=f"(hi) : "l"(v));
}
__device__ __forceinline__ u64 ffma2(u64 a, u64 b, u64 c) {
    u64 d; asm("fma.rn.f32x2 %0, %1, %2, %3;" : "=l"(d) : "l"(a), "l"(b), "l"(c));
    return d;
}

// ---------------------------------------------------------------------------
// 3x3 "same" conv, NCHW, input concatenated from up to 3 tensors along C.
// 32x32 spatial tile; 16x16 threads, each computing a 2x2 pixel micro-tile
// for 8 output channels. The 2 horizontal pixels live in one packed f32x2
// lane; weights are staged in smem pre-duplicated {w,w} so LDS feeds FFMA2
// directly. 2 input channels per sync pair.
// ---------------------------------------------------------------------------
__global__ void __launch_bounds__(256) conv3x3_kernel(
    const float* __restrict__ inA, int nA,
    const float* __restrict__ inB, int nB,
    const float* __restrict__ inC, int nC,
    const float* __restrict__ wgt, const float* __restrict__ bias,
    float* __restrict__ out, int IC, int OC, int doLrelu)
{
    const int ocgCount = OC >> 3;
    const int bz  = blockIdx.z;
    const int b   = bz / ocgCount;
    const int oc0 = (bz - b * ocgCount) << 3;

    const int tx = threadIdx.x, ty = threadIdx.y;
    const int tid = ty * 16 + tx;
    const int h0 = blockIdx.y * 32, w0 = blockIdx.x * 32;

    __shared__ float  sP[2][34][36];    // 2 ics x (32+2 halo), padded row (even)
    __shared__ float2 sW2[2][8][10];    // 2 ics x 8 oc x 9 duplicated weights

    u64 acc2[8][2];
#pragma unroll
    for (int o = 0; o < 8; o++) { acc2[o][0] = 0ull; acc2[o][1] = 0ull; }

    for (int ic0 = 0; ic0 < IC; ic0 += 2) {
        __syncthreads();   // previous chunk's smem reads done
        // ---- stage 2 input-channel patches (34x34, zero-padded) ----
#pragma unroll
        for (int j = 0; j < 2; j++) {
            const int ic = ic0 + j;
            const float* src;
            if (ic < nA)            src = inA + ((size_t)(b * nA + ic)) * HW;
            else if (ic < nA + nB)  src = inB + ((size_t)(b * nB + (ic - nA))) * HW;
            else                    src = inC + ((size_t)(b * nC + (ic - nA - nB))) * HW;
            for (int i = tid; i < 34 * 34; i += 256) {
                int py = i / 34, px = i - py * 34;
                int gy = h0 + py - 1, gx = w0 + px - 1;
                float v = 0.f;
                if (gy >= 0 && gy < HH && gx >= 0 && gx < WW) v = src[gy * WW + gx];
                sP[j][py][px] = v;
            }
        }
        // ---- stage 2x8x9 duplicated weights ----
        if (tid < 144) {
            int j = tid / 72, r = tid - j * 72;
            int o = r / 9, q = r - o * 9;
            float w = wgt[((size_t)(oc0 + o) * IC + (ic0 + j)) * 9 + q];
            sW2[j][o][q] = make_float2(w, w);
        }
        __syncthreads();

#pragma unroll
        for (int j = 0; j < 2; j++) {
            // 4 rows x 3 packed cols covering this thread's 2x2 pixels
            // P[row][dc] = {v[row][dc], v[row][dc+1]}
            u64 P[4][3];
#pragma unroll
            for (int r = 0; r < 4; r++) {
                float2 a = *(const float2*)&sP[j][2 * ty + r][2 * tx + 0];
                float2 c = *(const float2*)&sP[j][2 * ty + r][2 * tx + 2];
                P[r][0] = pk2(a.x, a.y);
                P[r][1] = pk2(a.y, c.x);
                P[r][2] = pk2(c.x, c.y);
            }

#pragma unroll
            for (int o = 0; o < 8; o++) {
                const ulonglong2* wq = (const ulonglong2*)&sW2[j][o][0];
                ulonglong2 w01 = wq[0];   // taps 0,1
                ulonglong2 w23 = wq[1];   // taps 2,3
                ulonglong2 w45 = wq[2];   // taps 4,5
                ulonglong2 w67 = wq[3];   // taps 6,7
                u64 w8 = *(const u64*)&sW2[j][o][8];
#pragma unroll
                for (int r = 0; r < 2; r++) {
                    u64 a = acc2[o][r];
                    a = ffma2(P[r + 0][0], w01.x, a);
                    a = ffma2(P[r + 0][1], w01.y, a);
                    a = ffma2(P[r + 0][2], w23.x, a);
                    a = ffma2(P[r + 1][0], w23.y, a);
                    a = ffma2(P[r + 1][1], w45.x, a);
                    a = ffma2(P[r + 1][2], w45.y, a);
                    a = ffma2(P[r + 2][0], w67.x, a);
                    a = ffma2(P[r + 2][1], w67.y, a);
                    a = ffma2(P[r + 2][2], w8,    a);
                    acc2[o][r] = a;
                }
            }
        }
    }

    // ---- epilogue: bias, lrelu, float2 stores ----
#pragma unroll
    for (int o = 0; o < 8; o++) {
        float bv = bias[oc0 + o];
        float* dst = out + ((size_t)(b * OC + oc0 + o)) * HW;
#pragma unroll
        for (int r = 0; r < 2; r++) {
            float r0, r1;
            upk2(acc2[o][r], r0, r1);
            r0 += bv; r1 += bv;
            if (doLrelu) {
                r0 = (r0 >= 0.f) ? r0 : 0.1f * r0;
                r1 = (r1 >= 0.f) ? r1 : 0.1f * r1;
            }
            *(float2*)&dst[(h0 + 2 * ty + r) * WW + (w0 + 2 * tx)] = make_float2(r0, r1);
        }
    }
}

// ---------------------------------------------------------------------------
// Repack dcn_w [o][g*8+c][k] into g_dcnw[((g*9+k)*8 + c)*64 + o]
// so the DCN kernel reads weights contiguously over o (packed-pair friendly).
// ---------------------------------------------------------------------------
__global__ void repack_dcnw_kernel(const float* __restrict__ w)
{
    int i = blockIdx.x * blockDim.x + threadIdx.x;   // 0 .. 36863
    if (i >= 8 * 9 * 8 * 64) return;
    int gk  = i >> 9;          // (g*9+k)
    int rem = i & 511;
    int c = rem >> 6;          // 0..7
    int o = rem & 63;          // 0..63
    int g = gk / 9, k = gk - g * 9;
    g_dcnw[i] = w[(size_t)o * 576 + (g * 8 + c) * 9 + k];
}

// ---------------------------------------------------------------------------
// Modulated deformable conv (+ offset assembly, sigmoid mask, final lrelu).
// One thread per pixel; 64 outputs as 32 packed f32x2 channel pairs.
// Per-g weight slab [k][c][o] staged in smem.
// ---------------------------------------------------------------------------
__global__ void __launch_bounds__(256, 2) dcn_kernel(
    const float* __restrict__ feat,    // ref_fea2X [B,64,H,W]
    const float* __restrict__ om,      // [B,216,H,W]
    const float* __restrict__ flows,   // [B,2,H,W]
    const float* __restrict__ bias,    // [64]
    float* __restrict__ out)           // [B,64,H,W]
{
    const int b  = blockIdx.z;
    const int tx = threadIdx.x, ty = threadIdx.y;
    const int tid = ty * 16 + tx;
    const int h = blockIdx.y * 16 + ty;
    const int w = blockIdx.x * 16 + tx;
    const int pix = h * WW + w;

    __shared__ float sWg[9 * 512];     // one g: [k][c][o]

    u64 accp[32];                      // accp[i] = {acc[2i], acc[2i+1]}
#pragma unroll
    for (int i = 0; i < 32; i++) accp[i] = 0ull;

    const float flowX = flows[(b * 2 + 0) * HW + pix];
    const float flowY = flows[(b * 2 + 1) * HW + pix];
    const float* omb = om   + (size_t)b * 216 * HW;
    const float* fb  = feat + (size_t)b * 64 * HW;

    for (int g = 0; g < 8; g++) {
        __syncthreads();
        {
            const float4* src4 = (const float4*)(g_dcnw + g * 9 * 512);
            float4* dst4 = (float4*)sWg;
            for (int j = tid; j < 9 * 128; j += 256) dst4[j] = src4[j];
        }
        __syncthreads();

        const float* fgc = fb + (g * 8) * HW;

#pragma unroll
        for (int k = 0; k < 9; k++) {
            const int kh = k / 3, kw = k - kh * 3;
            float dy = omb[(g * 18 + 2 * k + 0) * HW + pix] + flowY;
            float dx = omb[(g * 18 + 2 * k + 1) * HW + pix] + flowX;
            float mv = omb[(144 + g * 9 + k) * HW + pix];
            mv = 1.f / (1.f + __expf(-mv));

            float y = (float)h - 1.f + (float)kh + dy;
            float x = (float)w - 1.f + (float)kw + dx;
            float y0f = floorf(y), x0f = floorf(x);
            int y0 = (int)y0f, x0 = (int)x0f;
            float fy = y - y0f, fx = x - x0f;

            float w00 = (1.f - fy) * (1.f - fx);
            float w01 = (1.f - fy) * fx;
            float w10 = fy * (1.f - fx);
            float w11 = fy * fx;

            const bool iy0 = (y0 >= 0) && (y0 < HH);
            const bool iy1 = (y0 + 1 >= 0) && (y0 + 1 < HH);
            const bool ix0 = (x0 >= 0) && (x0 < WW);
            const bool ix1 = (x0 + 1 >= 0) && (x0 + 1 < WW);
            w00 = (iy0 && ix0) ? w00 * mv : 0.f;
            w01 = (iy0 && ix1) ? w01 * mv : 0.f;
            w10 = (iy1 && ix0) ? w10 * mv : 0.f;
            w11 = (iy1 && ix1) ? w11 * mv : 0.f;

            int yc0 = min(max(y0, 0), HH - 1);
            int yc1 = min(max(y0 + 1, 0), HH - 1);
            int xc0 = min(max(x0, 0), WW - 1);
            int xc1 = min(max(x0 + 1, 0), WW - 1);
            int i00 = yc0 * WW + xc0, i01 = yc0 * WW + xc1;
            int i10 = yc1 * WW + xc0, i11 = yc1 * WW + xc1;

            const float* wk = sWg + k * 512;
#pragma unroll
            for (int c = 0; c < 8; c++) {
                const float* fc = fgc + c * HW;
                float val = w00 * fc[i00] + w01 * fc[i01]
                          + w10 * fc[i10] + w11 * fc[i11];
                u64 vp = pk2(val, val);
                const ulonglong2* __restrict__ wrow =
                    (const ulonglong2*)(wk + c * 64);
#pragma unroll
                for (int q = 0; q < 16; q++) {
                    ulonglong2 wp = wrow[q];
                    accp[2 * q + 0] = ffma2(vp, wp.x, accp[2 * q + 0]);
                    accp[2 * q + 1] = ffma2(vp, wp.y, accp[2 * q + 1]);
                }
            }
        }
    }

#pragma unroll
    for (int i = 0; i < 32; i++) {
        float r0, r1;
        upk2(accp[i], r0, r1);
        r0 += bias[2 * i + 0];
        r1 += bias[2 * i + 1];
        r0 = (r0 >= 0.f) ? r0 : 0.1f * r0;
        r1 = (r1 >= 0.f) ? r1 : 0.1f * r1;
        out[((size_t)(b * 64 + 2 * i + 0)) * HW + pix] = r0;
        out[((size_t)(b * 64 + 2 * i + 1)) * HW + pix] = r1;
    }
}

// ---------------------------------------------------------------------------
extern "C" void kernel_launch(void* const* d_in, const int* in_sizes, int n_in,
                              void* d_out, int out_size)
{
    const float* ref_fea2X      = (const float*)d_in[0];
    const float* ref_fea2X_flow = (const float*)d_in[1];
    const float* lr_shake_fea   = (const float*)d_in[2];
    const float* flows          = (const float*)d_in[3];
    const float* w1             = (const float*)d_in[4];
    const float* b1             = (const float*)d_in[5];
    const float* w2             = (const float*)d_in[6];
    const float* b2             = (const float*)d_in[7];
    const float* w_om           = (const float*)d_in[8];
    const float* b_om           = (const float*)d_in[9];
    const float* dcn_w          = (const float*)d_in[10];
    const float* dcn_b          = (const float*)d_in[11];
    float* out = (float*)d_out;

    float *feat1, *feat2, *omb;
    cudaGetSymbolAddress((void**)&feat1, g_feat1);
    cudaGetSymbolAddress((void**)&feat2, g_feat2);
    cudaGetSymbolAddress((void**)&omb,   g_om);

    dim3 thr(16, 16);

    // conv1: concat(ref_fea2X_flow, lr_shake_fea, flows) 130 -> 64, lrelu
    conv3x3_kernel<<<dim3(4, 4, BB * (64 / 8)), thr>>>(
        ref_fea2X_flow, 64, lr_shake_fea, 64, flows, 2,
        w1, b1, feat1, 130, 64, 1);

    // conv2: 64 -> 64, lrelu
    conv3x3_kernel<<<dim3(4, 4, BB * (64 / 8)), thr>>>(
        feat1, 64, (const float*)0, 0, (const float*)0, 0,
        w2, b2, feat2, 64, 64, 1);

    // conv_om: 64 -> 216, raw
    conv3x3_kernel<<<dim3(4, 4, BB * (216 / 8)), thr>>>(
        feat2, 64, (const float*)0, 0, (const float*)0, 0,
        w_om, b_om, omb, 64, 216, 0);

    // repack dcn weights into [(g*9+k)][c][o]
    repack_dcnw_kernel<<<(8 * 9 * 8 * 64 + 255) / 256, 256>>>(dcn_w);

    // modulated deformable conv + lrelu
    dcn_kernel<<<dim3(8, 8, BB), thr>>>(ref_fea2X, omb, flows, dcn_b, out);
}

// round 6
// speedup vs baseline: 1.6111x; 1.6111x over previous
#include <cuda_runtime.h>
#include <math.h>

#define HH 128
#define WW 128
#define HW (HH * WW)
#define BB 2
#define NSTG 5   // ceil(34*34 / 256)

// ---------------- scratch (static device allocations; no runtime alloc) ----
__device__ float g_feat1[BB * 64 * HW];    // after conv1+lrelu
__device__ float g_feat2[BB * 64 * HW];    // after conv2+lrelu
__device__ float g_om[BB * 216 * HW];      // raw conv_om output
__device__ float g_dcnw[8 * 9 * 512];      // repacked dcn weights [(g*9+k)][o*8+c]

// ---------------------------------------------------------------------------
// 3x3 "same" conv, NCHW, input concatenated from up to 3 tensors along C.
// 32x32 spatial tile; 16x16 threads, each computing a 2x2 pixel micro-tile
// for 8 output channels. Double-buffered staging: chunk i+1's global loads
// are issued before chunk i's compute, so LDG latency hides under the FMA
// phase; one __syncthreads per chunk.
// ---------------------------------------------------------------------------
__global__ void __launch_bounds__(256) conv3x3_kernel(
    const float* __restrict__ inA, int nA,
    const float* __restrict__ inB, int nB,
    const float* __restrict__ inC, int nC,
    const float* __restrict__ wgt, const float* __restrict__ bias,
    float* __restrict__ out, int IC, int OC, int doLrelu)
{
    const int ocgCount = OC >> 3;
    const int bz  = blockIdx.z;
    const int b   = bz / ocgCount;
    const int oc0 = (bz - b * ocgCount) << 3;

    const int tx = threadIdx.x, ty = threadIdx.y;
    const int tid = ty * 16 + tx;
    const int h0 = blockIdx.y * 32, w0 = blockIdx.x * 32;

    __shared__ float sP[2][2][34][36];   // [buf][icSub][row][col]
    __shared__ float sW[2][2][8][12];    // [buf][icSub][oc][tap], padded

    // this thread's weight-staging assignment (fixed across chunks)
    const int wj = tid / 72;             // 0/1 (ic sub-index) when tid<144
    const int wr = tid - wj * 72;
    const int wo = wr / 9, wq = wr - wo * 9;
    const bool doW = (tid < 144);

    // ---- prefetch helpers ---------------------------------------------
    float stg[2][NSTG];
    float wv = 0.f;

    auto fetch = [&](int ic0) {
#pragma unroll
        for (int j = 0; j < 2; j++) {
            const int ic = ic0 + j;
            const float* src;
            if (ic < nA)            src = inA + ((size_t)(b * nA + ic)) * HW;
            else if (ic < nA + nB)  src = inB + ((size_t)(b * nB + (ic - nA))) * HW;
            else                    src = inC + ((size_t)(b * nC + (ic - nA - nB))) * HW;
#pragma unroll
            for (int s = 0; s < NSTG; s++) {
                int i = tid + s * 256;
                float v = 0.f;
                if (i < 34 * 34) {
                    int py = i / 34, px = i - py * 34;
                    int gy = h0 + py - 1, gx = w0 + px - 1;
                    if (gy >= 0 && gy < HH && gx >= 0 && gx < WW)
                        v = src[gy * WW + gx];
                }
                stg[j][s] = v;
            }
        }
        if (doW)
            wv = wgt[((size_t)(oc0 + wo) * IC + (ic0 + wj)) * 9 + wq];
    };

    auto store = [&](int buf) {
#pragma unroll
        for (int j = 0; j < 2; j++)
#pragma unroll
            for (int s = 0; s < NSTG; s++) {
                int i = tid + s * 256;
                if (i < 34 * 34) {
                    int py = i / 34, px = i - py * 34;
                    sP[buf][j][py][px] = stg[j][s];
                }
            }
        if (doW) sW[buf][wj][wo][wq] = wv;
    };

    float acc[8][4];
#pragma unroll
    for (int o = 0; o < 8; o++)
#pragma unroll
        for (int p = 0; p < 4; p++) acc[o][p] = 0.f;

    const int nChunks = IC >> 1;   // IC is even (130 / 64)

    // prologue: stage chunk 0
    fetch(0);
    store(0);
    __syncthreads();

    int buf = 0;
    for (int ch = 0; ch < nChunks; ch++) {
        const bool hasNext = (ch + 1 < nChunks);
        if (hasNext) fetch(2 * (ch + 1));   // LDGs in flight during compute

        // ---- compute from sP[buf] / sW[buf] ----
#pragma unroll
        for (int j = 0; j < 2; j++) {
            float v[4][4];
#pragma unroll
            for (int r = 0; r < 4; r++)
#pragma unroll
                for (int c = 0; c < 4; c++)
                    v[r][c] = sP[buf][j][2 * ty + r][2 * tx + c];

#pragma unroll
            for (int o = 0; o < 8; o++) {
                float4 wA = *(const float4*)&sW[buf][j][o][0];
                float4 wB = *(const float4*)&sW[buf][j][o][4];
                float  w8 = sW[buf][j][o][8];
#pragma unroll
                for (int r = 0; r < 2; r++)
#pragma unroll
                    for (int c = 0; c < 2; c++) {
                        float s;
                        s  = v[r + 0][c + 0] * wA.x;
                        s += v[r + 0][c + 1] * wA.y;
                        s += v[r + 0][c + 2] * wA.z;
                        s += v[r + 1][c + 0] * wA.w;
                        s += v[r + 1][c + 1] * wB.x;
                        s += v[r + 1][c + 2] * wB.y;
                        s += v[r + 2][c + 0] * wB.z;
                        s += v[r + 2][c + 1] * wB.w;
                        s += v[r + 2][c + 2] * w8;
                        acc[o][r * 2 + c] += s;
                    }
            }
        }

        if (hasNext) {
            store(buf ^ 1);       // other buffer: no conflict with this compute
            __syncthreads();
            buf ^= 1;
        }
    }

    // ---- epilogue: bias, lrelu, float2 stores ----
#pragma unroll
    for (int o = 0; o < 8; o++) {
        float bv = bias[oc0 + o];
        float* dst = out + ((size_t)(b * OC + oc0 + o)) * HW;
#pragma unroll
        for (int r = 0; r < 2; r++) {
            float r0 = acc[o][r * 2 + 0] + bv;
            float r1 = acc[o][r * 2 + 1] + bv;
            if (doLrelu) {
                r0 = (r0 >= 0.f) ? r0 : 0.1f * r0;
                r1 = (r1 >= 0.f) ? r1 : 0.1f * r1;
            }
            *(float2*)&dst[(h0 + 2 * ty + r) * WW + (w0 + 2 * tx)] = make_float2(r0, r1);
        }
    }
}

// ---------------------------------------------------------------------------
// Repack dcn_w [o][g*8+c][k] into g_dcnw[(g*9+k)*512 + o*8 + c].
// ---------------------------------------------------------------------------
__global__ void repack_dcnw_kernel(const float* __restrict__ w)
{
    int i = blockIdx.x * blockDim.x + threadIdx.x;   // 0 .. 36863
    if (i >= 8 * 9 * 512) return;
    int gk = i >> 9;           // g*9+k
    int oc = i & 511;          // o*8+c
    int g = gk / 9, k = gk - g * 9;
    int o = oc >> 3, c = oc & 7;
    g_dcnw[i] = w[(size_t)o * 576 + (g * 8 + c) * 9 + k];
}

// ---------------------------------------------------------------------------
// Modulated deformable conv (+ offset assembly, sigmoid mask, final lrelu).
// One thread per pixel; 64 fp32 accumulators; per-g weight slab in smem.
// ---------------------------------------------------------------------------
__global__ void __launch_bounds__(256, 2) dcn_kernel(
    const float* __restrict__ feat,    // ref_fea2X [B,64,H,W]
    const float* __restrict__ om,      // [B,216,H,W]
    const float* __restrict__ flows,   // [B,2,H,W]
    const float* __restrict__ bias,    // [64]
    float* __restrict__ out)           // [B,64,H,W]
{
    const int b  = blockIdx.z;
    const int tx = threadIdx.x, ty = threadIdx.y;
    const int tid = ty * 16 + tx;
    const int h = blockIdx.y * 16 + ty;
    const int w = blockIdx.x * 16 + tx;
    const int pix = h * WW + w;

    __shared__ float sWg[9 * 512];     // weights for one g: [k][o*8+c]

    float acc[64];
#pragma unroll
    for (int o = 0; o < 64; o++) acc[o] = 0.f;

    const float flowX = flows[(b * 2 + 0) * HW + pix];
    const float flowY = flows[(b * 2 + 1) * HW + pix];
    const float* omb = om   + (size_t)b * 216 * HW;
    const float* fb  = feat + (size_t)b * 64 * HW;

    for (int g = 0; g < 8; g++) {
        __syncthreads();
        {
            const float4* src4 = (const float4*)(g_dcnw + g * 9 * 512);
            float4* dst4 = (float4*)sWg;
            for (int j = tid; j < 9 * 128; j += 256) dst4[j] = src4[j];
        }
        __syncthreads();

        const float* fgc = fb + (g * 8) * HW;

#pragma unroll
        for (int k = 0; k < 9; k++) {
            const int kh = k / 3, kw = k - kh * 3;
            float dy = omb[(g * 18 + 2 * k + 0) * HW + pix] + flowY;
            float dx = omb[(g * 18 + 2 * k + 1) * HW + pix] + flowX;
            float mv = omb[(144 + g * 9 + k) * HW + pix];
            mv = 1.f / (1.f + __expf(-mv));

            float y = (float)h - 1.f + (float)kh + dy;
            float x = (float)w - 1.f + (float)kw + dx;
            float y0f = floorf(y), x0f = floorf(x);
            int y0 = (int)y0f, x0 = (int)x0f;
            float fy = y - y0f, fx = x - x0f;

            float w00 = (1.f - fy) * (1.f - fx);
            float w01 = (1.f - fy) * fx;
            float w10 = fy * (1.f - fx);
            float w11 = fy * fx;

            const bool iy0 = (y0 >= 0) && (y0 < HH);
            const bool iy1 = (y0 + 1 >= 0) && (y0 + 1 < HH);
            const bool ix0 = (x0 >= 0) && (x0 < WW);
            const bool ix1 = (x0 + 1 >= 0) && (x0 + 1 < WW);
            w00 = (iy0 && ix0) ? w00 * mv : 0.f;
            w01 = (iy0 && ix1) ? w01 * mv : 0.f;
            w10 = (iy1 && ix0) ? w10 * mv : 0.f;
            w11 = (iy1 && ix1) ? w11 * mv : 0.f;

            int yc0 = min(max(y0, 0), HH - 1);
            int yc1 = min(max(y0 + 1, 0), HH - 1);
            int xc0 = min(max(x0, 0), WW - 1);
            int xc1 = min(max(x0 + 1, 0), WW - 1);
            int i00 = yc0 * WW + xc0, i01 = yc0 * WW + xc1;
            int i10 = yc1 * WW + xc0, i11 = yc1 * WW + xc1;

            float val[8];
#pragma unroll
            for (int c = 0; c < 8; c++) {
                const float* fc = fgc + c * HW;
                val[c] = w00 * fc[i00] + w01 * fc[i01]
                       + w10 * fc[i10] + w11 * fc[i11];
            }

            const float4* sW4 = (const float4*)(sWg + k * 512);
#pragma unroll
            for (int o = 0; o < 64; o++) {
                float4 wa = sW4[o * 2 + 0];
                float4 wb = sW4[o * 2 + 1];
                acc[o] += val[0] * wa.x + val[1] * wa.y + val[2] * wa.z + val[3] * wa.w
                        + val[4] * wb.x + val[5] * wb.y + val[6] * wb.z + val[7] * wb.w;
            }
        }
    }

#pragma unroll
    for (int o = 0; o < 64; o++) {
        float r = acc[o] + bias[o];
        r = (r >= 0.f) ? r : 0.1f * r;
        out[((size_t)(b * 64 + o)) * HW + pix] = r;
    }
}

// ---------------------------------------------------------------------------
extern "C" void kernel_launch(void* const* d_in, const int* in_sizes, int n_in,
                              void* d_out, int out_size)
{
    const float* ref_fea2X      = (const float*)d_in[0];
    const float* ref_fea2X_flow = (const float*)d_in[1];
    const float* lr_shake_fea   = (const float*)d_in[2];
    const float* flows          = (const float*)d_in[3];
    const float* w1             = (const float*)d_in[4];
    const float* b1             = (const float*)d_in[5];
    const float* w2             = (const float*)d_in[6];
    const float* b2             = (const float*)d_in[7];
    const float* w_om           = (const float*)d_in[8];
    const float* b_om           = (const float*)d_in[9];
    const float* dcn_w          = (const float*)d_in[10];
    const float* dcn_b          = (const float*)d_in[11];
    float* out = (float*)d_out;

    float *feat1, *feat2, *omb;
    cudaGetSymbolAddress((void**)&feat1, g_feat1);
    cudaGetSymbolAddress((void**)&feat2, g_feat2);
    cudaGetSymbolAddress((void**)&omb,   g_om);

    dim3 thr(16, 16);

    // repack dcn weights FIRST (independent of convs; also shifts the ncu
    // capture slot onto conv_om instead of this trivial kernel)
    repack_dcnw_kernel<<<(8 * 9 * 512 + 255) / 256, 256>>>(dcn_w);

    // conv1: concat(ref_fea2X_flow, lr_shake_fea, flows) 130 -> 64, lrelu
    conv3x3_kernel<<<dim3(4, 4, BB * (64 / 8)), thr>>>(
        ref_fea2X_flow, 64, lr_shake_fea, 64, flows, 2,
        w1, b1, feat1, 130, 64, 1);

    // conv2: 64 -> 64, lrelu
    conv3x3_kernel<<<dim3(4, 4, BB * (64 / 8)), thr>>>(
        feat1, 64, (const float*)0, 0, (const float*)0, 0,
        w2, b2, feat2, 64, 64, 1);

    // conv_om: 64 -> 216, raw
    conv3x3_kernel<<<dim3(4, 4, BB * (216 / 8)), thr>>>(
        feat2, 64, (const float*)0, 0, (const float*)0, 0,
        w_om, b_om, omb, 64, 216, 0);

    // modulated deformable conv + lrelu
    dcn_kernel<<<dim3(8, 8, BB), thr>>>(ref_fea2X, omb, flows, dcn_b, out);
}

// round 8
// speedup vs baseline: 1.7583x; 1.0914x over previous
#include <cuda_runtime.h>
#include <math.h>

#define HH 128
#define WW 128
#define HW (HH * WW)
#define BB 2
#define NSTG 5   // ceil(34*34 / 256)

typedef unsigned int u32;

// ---------------- scratch (static device allocations; no runtime alloc) ----
__device__ float g_feat1[BB * 64 * HW];    // after conv1+lrelu
__device__ float g_feat2[BB * 64 * HW];    // after conv2+lrelu
__device__ float g_om[BB * 216 * HW];      // raw conv_om output
__device__ float g_dcnw[8 * 9 * 512];      // repacked dcn weights [(g*9+k)][o*8+c]

// ---------------- cp.async helpers ----------------------------------------
__device__ __forceinline__ u32 s2u(const void* p) {
    return (u32)__cvta_generic_to_shared(p);
}
__device__ __forceinline__ void cpasync4(u32 dst, const void* src, int srcsize) {
    asm volatile("cp.async.ca.shared.global [%0], [%1], 4, %2;\n"
                 :: "r"(dst), "l"(src), "r"(srcsize));
}
__device__ __forceinline__ void cpcommit() {
    asm volatile("cp.async.commit_group;\n");
}
template <int N>
__device__ __forceinline__ void cpwait() {
    asm volatile("cp.async.wait_group %0;\n" :: "n"(N));
}

// ---------------------------------------------------------------------------
// 3x3 "same" conv, NCHW, input concatenated from up to 3 tensors along C.
// 32x32 spatial tile; 16x16 threads, each computing a 2x2 pixel micro-tile
// for 8 output channels. Staging via cp.async double-buffering with
// precomputed per-thread offsets (no per-chunk bounds/ALU work, no register
// buffers). Patch reads are explicit float2 to avoid 2-way bank conflicts.
// ---------------------------------------------------------------------------
__global__ void __launch_bounds__(256, 2) conv3x3_kernel(
    const float* __restrict__ inA, int nA,
    const float* __restrict__ inB, int nB,
    const float* __restrict__ inC, int nC,
    const float* __restrict__ wgt, const float* __restrict__ bias,
    float* __restrict__ out, int IC, int OC, int doLrelu)
{
    const int ocgCount = OC >> 3;
    const int bz  = blockIdx.z;
    const int b   = bz / ocgCount;
    const int oc0 = (bz - b * ocgCount) << 3;

    const int tx = threadIdx.x, ty = threadIdx.y;
    const int tid = ty * 16 + tx;
    const int h0 = blockIdx.y * 32, w0 = blockIdx.x * 32;

    __shared__ float sP[2][2][34][36];   // [buf][icSub][row][col]
    __shared__ float sW[2][2][8][12];    // [buf][icSub][oc][tap], padded

    // ---- precompute per-thread staging plan (loop-invariant) ----------
    int  goff[NSTG];     // clamped global offset within one channel plane
    int  gsz[NSTG];      // 4 if in-bounds, else 0 (cp.async zero-fill)
    u32  sofs[NSTG];     // smem byte offset within one [buf][j] patch
    int  nElems = 0;     // how many staging slots this thread owns
#pragma unroll
    for (int s = 0; s < NSTG; s++) {
        int i = tid + s * 256;
        if (i < 34 * 34) {
            int py = i / 34, px = i - py * 34;
            int gy = h0 + py - 1, gx = w0 + px - 1;
            bool inb = (gy >= 0 && gy < HH && gx >= 0 && gx < WW);
            int gyc = min(max(gy, 0), HH - 1);
            int gxc = min(max(gx, 0), WW - 1);
            goff[s] = gyc * WW + gxc;
            gsz[s]  = inb ? 4 : 0;
            sofs[s] = (u32)((py * 36 + px) * 4);
            nElems = s + 1;
        }
    }
    const u32 sPbase = s2u(&sP[0][0][0][0]);
    const u32 patchBytes = 34 * 36 * 4;

    // weight staging assignment (tid<144): one element per chunk
    const int wj = tid / 72;
    const int wr = tid - wj * 72;
    const int wo = wr / 9, wq = wr - wo * 9;
    const bool doW = (tid < 144);
    const size_t wBase = ((size_t)(oc0 + wo) * IC + wj) * 9 + wq;   // + ic0*9
    const u32 sWbase = s2u(&sW[0][0][0][0]);
    const u32 sWofs  = (u32)(((wj * 8 + wo) * 12 + wq) * 4);
    const u32 sWbuf  = 2 * 8 * 12 * 4;

    // channel source pointers resolved per chunk (cheap: 2 selects)
    auto srcPtr = [&](int ic) -> const float* {
        if (ic < nA)           return inA + ((size_t)(b * nA + ic)) * HW;
        if (ic < nA + nB)      return inB + ((size_t)(b * nB + (ic - nA))) * HW;
        return inC + ((size_t)(b * nC + (ic - nA - nB))) * HW;
    };

    auto fetchAsync = [&](int buf, int ic0) {
#pragma unroll
        for (int j = 0; j < 2; j++) {
            const float* src = srcPtr(ic0 + j);
            const u32 dbase = sPbase + (u32)(buf * 2 + j) * patchBytes;
#pragma unroll
            for (int s = 0; s < NSTG; s++)
                if (s < nElems)
                    cpasync4(dbase + sofs[s], src + goff[s], gsz[s]);
        }
        if (doW)
            cpasync4(sWbase + (u32)buf * sWbuf + sWofs,
                     wgt + wBase + (size_t)ic0 * 9, 4);
    };

    float acc[8][4];
#pragma unroll
    for (int o = 0; o < 8; o++)
#pragma unroll
        for (int p = 0; p < 4; p++) acc[o][p] = 0.f;

    const int nChunks = IC >> 1;   // IC is even (130 / 64)

    fetchAsync(0, 0);
    cpcommit();

    int buf = 0;
    for (int ch = 0; ch < nChunks; ch++) {
        const bool hasNext = (ch + 1 < nChunks);
        if (hasNext) {
            fetchAsync(buf ^ 1, 2 * (ch + 1));
            cpcommit();
            cpwait<1>();           // chunk ch landed; ch+1 may stay in flight
        } else {
            cpwait<0>();
        }
        __syncthreads();

        // ---- compute from sP[buf] / sW[buf] ----
#pragma unroll
        for (int j = 0; j < 2; j++) {
            float v[4][4];
#pragma unroll
            for (int r = 0; r < 4; r++) {
                float2 a  = *(const float2*)&sP[buf][j][2 * ty + r][2 * tx + 0];
                float2 cc = *(const float2*)&sP[buf][j][2 * ty + r][2 * tx + 2];
                v[r][0] = a.x;  v[r][1] = a.y;
                v[r][2] = cc.x; v[r][3] = cc.y;
            }

#pragma unroll
            for (int o = 0; o < 8; o++) {
                float4 wA = *(const float4*)&sW[buf][j][o][0];
                float4 wB = *(const float4*)&sW[buf][j][o][4];
                float  w8 = sW[buf][j][o][8];
#pragma unroll
                for (int r = 0; r < 2; r++)
#pragma unroll
                    for (int c = 0; c < 2; c++) {
                        float s;
                        s  = v[r + 0][c + 0] * wA.x;
                        s += v[r + 0][c + 1] * wA.y;
                        s += v[r + 0][c + 2] * wA.z;
                        s += v[r + 1][c + 0] * wA.w;
                        s += v[r + 1][c + 1] * wB.x;
                        s += v[r + 1][c + 2] * wB.y;
                        s += v[r + 2][c + 0] * wB.z;
                        s += v[r + 2][c + 1] * wB.w;
                        s += v[r + 2][c + 2] * w8;
                        acc[o][r * 2 + c] += s;
                    }
            }
        }

        __syncthreads();   // all reads of buf done before it is re-filled
        buf ^= 1;
    }

    // ---- epilogue: bias, lrelu, float2 stores ----
#pragma unroll
    for (int o = 0; o < 8; o++) {
        float bv = bias[oc0 + o];
        float* dst = out + ((size_t)(b * OC + oc0 + o)) * HW;
#pragma unroll
        for (int r = 0; r < 2; r++) {
            float r0 = acc[o][r * 2 + 0] + bv;
            float r1 = acc[o][r * 2 + 1] + bv;
            if (doLrelu) {
                r0 = (r0 >= 0.f) ? r0 : 0.1f * r0;
                r1 = (r1 >= 0.f) ? r1 : 0.1f * r1;
            }
            *(float2*)&dst[(h0 + 2 * ty + r) * WW + (w0 + 2 * tx)] = make_float2(r0, r1);
        }
    }
}

// ---------------------------------------------------------------------------
// Repack dcn_w [o][g*8+c][k] into g_dcnw[(g*9+k)*512 + o*8 + c].
// ---------------------------------------------------------------------------
__global__ void repack_dcnw_kernel(const float* __restrict__ w)
{
    int i = blockIdx.x * blockDim.x + threadIdx.x;   // 0 .. 36863
    if (i >= 8 * 9 * 512) return;
    int gk = i >> 9;           // g*9+k
    int oc = i & 511;          // o*8+c
    int g = gk / 9, k = gk - g * 9;
    int o = oc >> 3, c = oc & 7;
    g_dcnw[i] = w[(size_t)o * 576 + (g * 8 + c) * 9 + k];
}

// ---------------------------------------------------------------------------
// Modulated deformable conv (+ offset assembly, sigmoid mask, final lrelu).
// One thread per pixel; 64 fp32 accumulators; per-g weight slab in smem.
// ---------------------------------------------------------------------------
__global__ void __launch_bounds__(256, 2) dcn_kernel(
    const float* __restrict__ feat,    // ref_fea2X [B,64,H,W]
    const float* __restrict__ om,      // [B,216,H,W]
    const float* __restrict__ flows,   // [B,2,H,W]
    const float* __restrict__ bias,    // [64]
    float* __restrict__ out)           // [B,64,H,W]
{
    const int b  = blockIdx.z;
    const int tx = threadIdx.x, ty = threadIdx.y;
    const int tid = ty * 16 + tx;
    const int h = blockIdx.y * 16 + ty;
    const int w = blockIdx.x * 16 + tx;
    const int pix = h * WW + w;

    __shared__ float sWg[9 * 512];     // weights for one g: [k][o*8+c]

    float acc[64];
#pragma unroll
    for (int o = 0; o < 64; o++) acc[o] = 0.f;

    const float flowX = flows[(b * 2 + 0) * HW + pix];
    const float flowY = flows[(b * 2 + 1) * HW + pix];
    const float* omb = om   + (size_t)b * 216 * HW;
    const float* fb  = feat + (size_t)b * 64 * HW;

    for (int g = 0; g < 8; g++) {
        __syncthreads();
        {
            const float4* src4 = (const float4*)(g_dcnw + g * 9 * 512);
            float4* dst4 = (float4*)sWg;
            for (int j = tid; j < 9 * 128; j += 256) dst4[j] = src4[j];
        }
        __syncthreads();

        const float* fgc = fb + (g * 8) * HW;

#pragma unroll
        for (int k = 0; k < 9; k++) {
            const int kh = k / 3, kw = k - kh * 3;
            float dy = omb[(g * 18 + 2 * k + 0) * HW + pix] + flowY;
            float dx = omb[(g * 18 + 2 * k + 1) * HW + pix] + flowX;
            float mv = omb[(144 + g * 9 + k) * HW + pix];
            mv = 1.f / (1.f + __expf(-mv));

            float y = (float)h - 1.f + (float)kh + dy;
            float x = (float)w - 1.f + (float)kw + dx;
            float y0f = floorf(y), x0f = floorf(x);
            int y0 = (int)y0f, x0 = (int)x0f;
            float fy = y - y0f, fx = x - x0f;

            float w00 = (1.f - fy) * (1.f - fx);
            float w01 = (1.f - fy) * fx;
            float w10 = fy * (1.f - fx);
            float w11 = fy * fx;

            const bool iy0 = (y0 >= 0) && (y0 < HH);
            const bool iy1 = (y0 + 1 >= 0) && (y0 + 1 < HH);
            const bool ix0 = (x0 >= 0) && (x0 < WW);
            const bool ix1 = (x0 + 1 >= 0) && (x0 + 1 < WW);
            w00 = (iy0 && ix0) ? w00 * mv : 0.f;
            w01 = (iy0 && ix1) ? w01 * mv : 0.f;
            w10 = (iy1 && ix0) ? w10 * mv : 0.f;
            w11 = (iy1 && ix1) ? w11 * mv : 0.f;

            int yc0 = min(max(y0, 0), HH - 1);
            int yc1 = min(max(y0 + 1, 0), HH - 1);
            int xc0 = min(max(x0, 0), WW - 1);
            int xc1 = min(max(x0 + 1, 0), WW - 1);
            int i00 = yc0 * WW + xc0, i01 = yc0 * WW + xc1;
            int i10 = yc1 * WW + xc0, i11 = yc1 * WW + xc1;

            float val[8];
#pragma unroll
            for (int c = 0; c < 8; c++) {
                const float* fc = fgc + c * HW;
                val[c] = w00 * fc[i00] + w01 * fc[i01]
                       + w10 * fc[i10] + w11 * fc[i11];
            }

            const float4* sW4 = (const float4*)(sWg + k * 512);
#pragma unroll
            for (int o = 0; o < 64; o++) {
                float4 wa = sW4[o * 2 + 0];
                float4 wb = sW4[o * 2 + 1];
                acc[o] += val[0] * wa.x + val[1] * wa.y + val[2] * wa.z + val[3] * wa.w
                        + val[4] * wb.x + val[5] * wb.y + val[6] * wb.z + val[7] * wb.w;
            }
        }
    }

#pragma unroll
    for (int o = 0; o < 64; o++) {
        float r = acc[o] + bias[o];
        r = (r >= 0.f) ? r : 0.1f * r;
        out[((size_t)(b * 64 + o)) * HW + pix] = r;
    }
}

// ---------------------------------------------------------------------------
extern "C" void kernel_launch(void* const* d_in, const int* in_sizes, int n_in,
                              void* d_out, int out_size)
{
    const float* ref_fea2X      = (const float*)d_in[0];
    const float* ref_fea2X_flow = (const float*)d_in[1];
    const float* lr_shake_fea   = (const float*)d_in[2];
    const float* flows          = (const float*)d_in[3];
    const float* w1             = (const float*)d_in[4];
    const float* b1             = (const float*)d_in[5];
    const float* w2             = (const float*)d_in[6];
    const float* b2             = (const float*)d_in[7];
    const float* w_om           = (const float*)d_in[8];
    const float* b_om           = (const float*)d_in[9];
    const float* dcn_w          = (const float*)d_in[10];
    const float* dcn_b          = (const float*)d_in[11];
    float* out = (float*)d_out;

    float *feat1, *feat2, *omb;
    cudaGetSymbolAddress((void**)&feat1, g_feat1);
    cudaGetSymbolAddress((void**)&feat2, g_feat2);
    cudaGetSymbolAddress((void**)&omb,   g_om);

    dim3 thr(16, 16);

    // repack dcn weights first (independent; keeps ncu slot on a heavy kernel)
    repack_dcnw_kernel<<<(8 * 9 * 512 + 255) / 256, 256>>>(dcn_w);

    // conv1: concat(ref_fea2X_flow, lr_shake_fea, flows) 130 -> 64, lrelu
    conv3x3_kernel<<<dim3(4, 4, BB * (64 / 8)), thr>>>(
        ref_fea2X_flow, 64, lr_shake_fea, 64, flows, 2,
        w1, b1, feat1, 130, 64, 1);

    // conv2: 64 -> 64, lrelu
    conv3x3_kernel<<<dim3(4, 4, BB * (64 / 8)), thr>>>(
        feat1, 64, (const float*)0, 0, (const float*)0, 0,
        w2, b2, feat2, 64, 64, 1);

    // conv_om: 64 -> 216, raw
    conv3x3_kernel<<<dim3(4, 4, BB * (216 / 8)), thr>>>(
        feat2, 64, (const float*)0, 0, (const float*)0, 0,
        w_om, b_om, omb, 64, 216, 0);

    // modulated deformable conv + lrelu
    dcn_kernel<<<dim3(8, 8, BB), thr>>>(ref_fea2X, omb, flows, dcn_b, out);
}

// round 9
// speedup vs baseline: 1.7745x; 1.0092x over previous
#include <cuda_runtime.h>
#include <math.h>

#define HH 128
#define WW 128
#define HW (HH * WW)
#define BB 2
#define NSTG 5   // ceil(34*34 / 256)

typedef unsigned int u32;

// ---------------- scratch (static device allocations; no runtime alloc) ----
__device__ float g_feat1[BB * 64 * HW];    // after conv1+lrelu
__device__ float g_feat2[BB * 64 * HW];    // after conv2+lrelu
__device__ float g_om[BB * 216 * HW];      // raw conv_om output
__device__ float g_dcnw[8 * 9 * 512];      // repacked dcn weights [(g*9+k)][o*8+c]

// ---------------- cp.async helpers ----------------------------------------
__device__ __forceinline__ u32 s2u(const void* p) {
    return (u32)__cvta_generic_to_shared(p);
}
__device__ __forceinline__ void cpasync4(u32 dst, const void* src, int srcsize) {
    asm volatile("cp.async.ca.shared.global [%0], [%1], 4, %2;\n"
                 :: "r"(dst), "l"(src), "r"(srcsize));
}
__device__ __forceinline__ void cpasync16(u32 dst, const void* src) {
    asm volatile("cp.async.cg.shared.global [%0], [%1], 16;\n"
                 :: "r"(dst), "l"(src));
}
__device__ __forceinline__ void cpcommit() {
    asm volatile("cp.async.commit_group;\n");
}
template <int N>
__device__ __forceinline__ void cpwait() {
    asm volatile("cp.async.wait_group %0;\n" :: "n"(N));
}

// ---------------------------------------------------------------------------
// 3x3 "same" conv, NCHW, concat input. 32x32 tile; 16x16 threads; 2x2 pixel
// micro-tile x 8 oc per thread. THREE-stage cp.async ring, single barrier
// per chunk: wait(ch) -> barrier -> issue fetch(ch+2) -> compute(ch).
// The fetch into buffer (ch+2)%3 == (ch-1)%3 is ordered after barrier(ch),
// hence after all reads of that buffer in iteration ch-1.
// ---------------------------------------------------------------------------
__global__ void __launch_bounds__(256, 2) conv3x3_kernel(
    const float* __restrict__ inA, int nA,
    const float* __restrict__ inB, int nB,
    const float* __restrict__ inC, int nC,
    const float* __restrict__ wgt, const float* __restrict__ bias,
    float* __restrict__ out, int IC, int OC, int doLrelu)
{
    const int ocgCount = OC >> 3;
    const int bz  = blockIdx.z;
    const int b   = bz / ocgCount;
    const int oc0 = (bz - b * ocgCount) << 3;

    const int tx = threadIdx.x, ty = threadIdx.y;
    const int tid = ty * 16 + tx;
    const int h0 = blockIdx.y * 32, w0 = blockIdx.x * 32;

    __shared__ float sP[3][2][34][36];   // [ring][icSub][row][col]
    __shared__ float sW[3][2][8][12];    // [ring][icSub][oc][tap], padded

    // ---- precompute per-thread staging plan (loop-invariant) ----------
    int  goff[NSTG];
    int  gsz[NSTG];
    u32  sofs[NSTG];
    int  nElems = 0;
#pragma unroll
    for (int s = 0; s < NSTG; s++) {
        int i = tid + s * 256;
        if (i < 34 * 34) {
            int py = i / 34, px = i - py * 34;
            int gy = h0 + py - 1, gx = w0 + px - 1;
            bool inb = (gy >= 0 && gy < HH && gx >= 0 && gx < WW);
            int gyc = min(max(gy, 0), HH - 1);
            int gxc = min(max(gx, 0), WW - 1);
            goff[s] = gyc * WW + gxc;
            gsz[s]  = inb ? 4 : 0;
            sofs[s] = (u32)((py * 36 + px) * 4);
            nElems = s + 1;
        }
    }
    const u32 sPbase = s2u(&sP[0][0][0][0]);
    const u32 patchBytes = 34 * 36 * 4;

    const int wj = tid / 72;
    const int wr = tid - wj * 72;
    const int wo = wr / 9, wq = wr - wo * 9;
    const bool doW = (tid < 144);
    const size_t wBase = ((size_t)(oc0 + wo) * IC + wj) * 9 + wq;   // + ic0*9
    const u32 sWbase = s2u(&sW[0][0][0][0]);
    const u32 sWofs  = (u32)(((wj * 8 + wo) * 12 + wq) * 4);
    const u32 sWbuf  = 2 * 8 * 12 * 4;

    auto srcPtr = [&](int ic) -> const float* {
        if (ic < nA)           return inA + ((size_t)(b * nA + ic)) * HW;
        if (ic < nA + nB)      return inB + ((size_t)(b * nB + (ic - nA))) * HW;
        return inC + ((size_t)(b * nC + (ic - nA - nB))) * HW;
    };

    auto fetchAsync = [&](int ring, int ic0) {
#pragma unroll
        for (int j = 0; j < 2; j++) {
            const float* src = srcPtr(ic0 + j);
            const u32 dbase = sPbase + (u32)(ring * 2 + j) * patchBytes;
#pragma unroll
            for (int s = 0; s < NSTG; s++)
                if (s < nElems)
                    cpasync4(dbase + sofs[s], src + goff[s], gsz[s]);
        }
        if (doW)
            cpasync4(sWbase + (u32)ring * sWbuf + sWofs,
                     wgt + wBase + (size_t)ic0 * 9, 4);
    };

    float acc[8][4];
#pragma unroll
    for (int o = 0; o < 8; o++)
#pragma unroll
        for (int p = 0; p < 4; p++) acc[o][p] = 0.f;

    const int nChunks = IC >> 1;   // IC even (130 / 64)

    // prologue: chunks 0 and 1 in flight
    fetchAsync(0, 0);
    cpcommit();
    if (nChunks > 1) { fetchAsync(1, 2); cpcommit(); }

    for (int ch = 0; ch < nChunks; ch++) {
        const int ring = ch % 3;
        if (ch + 1 < nChunks) cpwait<1>(); else cpwait<0>();
        __syncthreads();
        if (ch + 2 < nChunks) {         // issued AFTER the barrier (race-free)
            fetchAsync((ch + 2) % 3, 2 * (ch + 2));
            cpcommit();
        }

        // ---- compute from sP[ring] / sW[ring] ----
#pragma unroll
        for (int j = 0; j < 2; j++) {
            float v[4][4];
#pragma unroll
            for (int r = 0; r < 4; r++) {
                float2 a  = *(const float2*)&sP[ring][j][2 * ty + r][2 * tx + 0];
                float2 cc = *(const float2*)&sP[ring][j][2 * ty + r][2 * tx + 2];
                v[r][0] = a.x;  v[r][1] = a.y;
                v[r][2] = cc.x; v[r][3] = cc.y;
            }

#pragma unroll
            for (int o = 0; o < 8; o++) {
                float4 wA = *(const float4*)&sW[ring][j][o][0];
                float4 wB = *(const float4*)&sW[ring][j][o][4];
                float  w8 = sW[ring][j][o][8];
#pragma unroll
                for (int r = 0; r < 2; r++)
#pragma unroll
                    for (int c = 0; c < 2; c++) {
                        float s;
                        s  = v[r + 0][c + 0] * wA.x;
                        s += v[r + 0][c + 1] * wA.y;
                        s += v[r + 0][c + 2] * wA.z;
                        s += v[r + 1][c + 0] * wA.w;
                        s += v[r + 1][c + 1] * wB.x;
                        s += v[r + 1][c + 2] * wB.y;
                        s += v[r + 2][c + 0] * wB.z;
                        s += v[r + 2][c + 1] * wB.w;
                        s += v[r + 2][c + 2] * w8;
                        acc[o][r * 2 + c] += s;
                    }
            }
        }
    }

    // ---- epilogue: bias, lrelu, float2 stores ----
#pragma unroll
    for (int o = 0; o < 8; o++) {
        float bv = bias[oc0 + o];
        float* dst = out + ((size_t)(b * OC + oc0 + o)) * HW;
#pragma unroll
        for (int r = 0; r < 2; r++) {
            float r0 = acc[o][r * 2 + 0] + bv;
            float r1 = acc[o][r * 2 + 1] + bv;
            if (doLrelu) {
                r0 = (r0 >= 0.f) ? r0 : 0.1f * r0;
                r1 = (r1 >= 0.f) ? r1 : 0.1f * r1;
            }
            *(float2*)&dst[(h0 + 2 * ty + r) * WW + (w0 + 2 * tx)] = make_float2(r0, r1);
        }
    }
}

// ---------------------------------------------------------------------------
// Repack dcn_w [o][g*8+c][k] into g_dcnw[(g*9+k)*512 + o*8 + c].
// ---------------------------------------------------------------------------
__global__ void repack_dcnw_kernel(const float* __restrict__ w)
{
    int i = blockIdx.x * blockDim.x + threadIdx.x;   // 0 .. 36863
    if (i >= 8 * 9 * 512) return;
    int gk = i >> 9;           // g*9+k
    int oc = i & 511;          // o*8+c
    int g = gk / 9, k = gk - g * 9;
    int o = oc >> 3, c = oc & 7;
    g_dcnw[i] = w[(size_t)o * 576 + (g * 8 + c) * 9 + k];
}

// ---------------------------------------------------------------------------
// Modulated deformable conv. One thread per pixel; 64 fp32 accumulators.
// Per-g weight slab double-buffered via cp.async: one barrier per g, and
// g+1's slab streams in while g computes.
// ---------------------------------------------------------------------------
__global__ void __launch_bounds__(256, 2) dcn_kernel(
    const float* __restrict__ feat,    // ref_fea2X [B,64,H,W]
    const float* __restrict__ om,      // [B,216,H,W]
    const float* __restrict__ flows,   // [B,2,H,W]
    const float* __restrict__ bias,    // [64]
    float* __restrict__ out)           // [B,64,H,W]
{
    const int b  = blockIdx.z;
    const int tx = threadIdx.x, ty = threadIdx.y;
    const int tid = ty * 16 + tx;
    const int h = blockIdx.y * 16 + ty;
    const int w = blockIdx.x * 16 + tx;
    const int pix = h * WW + w;

    __shared__ float sWg[2][9 * 512];  // double-buffered [k][o*8+c] slabs

    const u32 sWgBase = s2u(&sWg[0][0]);
    const u32 slabBytes = 9 * 512 * 4;

    auto stageSlab = [&](int buf, int g) {
        const float* src = g_dcnw + (size_t)g * 9 * 512;
        const u32 dst = sWgBase + (u32)buf * slabBytes;
        for (int j = tid; j < 9 * 128; j += 256)          // float4 granules
            cpasync16(dst + (u32)j * 16, src + (size_t)j * 4);
    };

    float acc[64];
#pragma unroll
    for (int o = 0; o < 64; o++) acc[o] = 0.f;

    const float flowX = flows[(b * 2 + 0) * HW + pix];
    const float flowY = flows[(b * 2 + 1) * HW + pix];
    const float* omb = om   + (size_t)b * 216 * HW;
    const float* fb  = feat + (size_t)b * 64 * HW;

    stageSlab(0, 0);
    cpcommit();

    for (int g = 0; g < 8; g++) {
        const int buf = g & 1;
        cpwait<0>();               // drain slab g (committed last iter / prologue)
        __syncthreads();           // all threads: slab visible, prev buf free
        if (g + 1 < 8) {           // prefetch g+1 while computing g
            stageSlab(buf ^ 1, g + 1);
            cpcommit();
        }

        const float* fgc = fb + (g * 8) * HW;
        const float* wslab = &sWg[buf][0];

#pragma unroll
        for (int k = 0; k < 9; k++) {
            const int kh = k / 3, kw = k - kh * 3;
            float dy = omb[(g * 18 + 2 * k + 0) * HW + pix] + flowY;
            float dx = omb[(g * 18 + 2 * k + 1) * HW + pix] + flowX;
            float mv = omb[(144 + g * 9 + k) * HW + pix];
            mv = 1.f / (1.f + __expf(-mv));

            float y = (float)h - 1.f + (float)kh + dy;
            float x = (float)w - 1.f + (float)kw + dx;
            float y0f = floorf(y), x0f = floorf(x);
            int y0 = (int)y0f, x0 = (int)x0f;
            float fy = y - y0f, fx = x - x0f;

            float w00 = (1.f - fy) * (1.f - fx);
            float w01 = (1.f - fy) * fx;
            float w10 = fy * (1.f - fx);
            float w11 = fy * fx;

            const bool iy0 = (y0 >= 0) && (y0 < HH);
            const bool iy1 = (y0 + 1 >= 0) && (y0 + 1 < HH);
            const bool ix0 = (x0 >= 0) && (x0 < WW);
            const bool ix1 = (x0 + 1 >= 0) && (x0 + 1 < WW);
            w00 = (iy0 && ix0) ? w00 * mv : 0.f;
            w01 = (iy0 && ix1) ? w01 * mv : 0.f;
            w10 = (iy1 && ix0) ? w10 * mv : 0.f;
            w11 = (iy1 && ix1) ? w11 * mv : 0.f;

            int yc0 = min(max(y0, 0), HH - 1);
            int yc1 = min(max(y0 + 1, 0), HH - 1);
            int xc0 = min(max(x0, 0), WW - 1);
            int xc1 = min(max(x0 + 1, 0), WW - 1);
            int i00 = yc0 * WW + xc0, i01 = yc0 * WW + xc1;
            int i10 = yc1 * WW + xc0, i11 = yc1 * WW + xc1;

            float val[8];
#pragma unroll
            for (int c = 0; c < 8; c++) {
                const float* fc = fgc + c * HW;
                val[c] = w00 * fc[i00] + w01 * fc[i01]
                       + w10 * fc[i10] + w11 * fc[i11];
            }

            const float4* sW4 = (const float4*)(wslab + k * 512);
#pragma unroll
            for (int o = 0; o < 64; o++) {
                float4 wa = sW4[o * 2 + 0];
                float4 wb = sW4[o * 2 + 1];
                acc[o] += val[0] * wa.x + val[1] * wa.y + val[2] * wa.z + val[3] * wa.w
                        + val[4] * wb.x + val[5] * wb.y + val[6] * wb.z + val[7] * wb.w;
            }
        }
    }

#pragma unroll
    for (int o = 0; o < 64; o++) {
        float r = acc[o] + bias[o];
        r = (r >= 0.f) ? r : 0.1f * r;
        out[((size_t)(b * 64 + o)) * HW + pix] = r;
    }
}

// ---------------------------------------------------------------------------
extern "C" void kernel_launch(void* const* d_in, const int* in_sizes, int n_in,
                              void* d_out, int out_size)
{
    const float* ref_fea2X      = (const float*)d_in[0];
    const float* ref_fea2X_flow = (const float*)d_in[1];
    const float* lr_shake_fea   = (const float*)d_in[2];
    const float* flows          = (const float*)d_in[3];
    const float* w1             = (const float*)d_in[4];
    const float* b1             = (const float*)d_in[5];
    const float* w2             = (const float*)d_in[6];
    const float* b2             = (const float*)d_in[7];
    const float* w_om           = (const float*)d_in[8];
    const float* b_om           = (const float*)d_in[9];
    const float* dcn_w          = (const float*)d_in[10];
    const float* dcn_b          = (const float*)d_in[11];
    float* out = (float*)d_out;

    float *feat1, *feat2, *omb;
    cudaGetSymbolAddress((void**)&feat1, g_feat1);
    cudaGetSymbolAddress((void**)&feat2, g_feat2);
    cudaGetSymbolAddress((void**)&omb,   g_om);

    dim3 thr(16, 16);

    // repack dcn weights first (independent; keeps ncu slot on a heavy kernel)
    repack_dcnw_kernel<<<(8 * 9 * 512 + 255) / 256, 256>>>(dcn_w);

    // conv1: concat(ref_fea2X_flow, lr_shake_fea, flows) 130 -> 64, lrelu
    conv3x3_kernel<<<dim3(4, 4, BB * (64 / 8)), thr>>>(
        ref_fea2X_flow, 64, lr_shake_fea, 64, flows, 2,
        w1, b1, feat1, 130, 64, 1);

    // conv2: 64 -> 64, lrelu
    conv3x3_kernel<<<dim3(4, 4, BB * (64 / 8)), thr>>>(
        feat1, 64, (const float*)0, 0, (const float*)0, 0,
        w2, b2, feat2, 64, 64, 1);

    // conv_om: 64 -> 216, raw
    conv3x3_kernel<<<dim3(4, 4, BB * (216 / 8)), thr>>>(
        feat2, 64, (const float*)0, 0, (const float*)0, 0,
        w_om, b_om, omb, 64, 216, 0);

    // modulated deformable conv + lrelu
    dcn_kernel<<<dim3(8, 8, BB), thr>>>(ref_fea2X, omb, flows, dcn_b, out);
}

// round 10
// speedup vs baseline: 2.9892x; 1.6845x over previous
#include <cuda_runtime.h>
#include <math.h>

#define HH 128
#define WW 128
#define HW (HH * WW)
#define BB 2

typedef unsigned int u32;

// ---------------- scratch (static device allocations; no runtime alloc) ----
__device__ float g_feat1[BB * 64 * HW];     // after conv1+lrelu
__device__ float g_feat2[BB * 64 * HW];     // after conv2+lrelu
__device__ float g_om[BB * 216 * HW];       // raw conv_om output
__device__ float g_dcnw[8 * 9 * 512];       // dcn weights [(g*9+k)][o*8+c]
// repacked conv weights, tf32-rounded: [z][chunk][tap][k8][oc40]
__device__ float g_wc1[2 * 17 * 2880];
__device__ float g_wc2[2 * 8 * 2880];
__device__ float g_wom[7 * 8 * 2880];

// ---------------- cp.async helpers ----------------------------------------
__device__ __forceinline__ u32 s2u(const void* p) {
    return (u32)__cvta_generic_to_shared(p);
}
__device__ __forceinline__ void cpasync4(u32 dst, const void* src, int srcsize) {
    asm volatile("cp.async.ca.shared.global [%0], [%1], 4, %2;\n"
                 :: "r"(dst), "l"(src), "r"(srcsize));
}
__device__ __forceinline__ void cpasync16(u32 dst, const void* src) {
    asm volatile("cp.async.cg.shared.global [%0], [%1], 16;\n"
                 :: "r"(dst), "l"(src));
}
__device__ __forceinline__ void cpcommit() {
    asm volatile("cp.async.commit_group;\n");
}
template <int N>
__device__ __forceinline__ void cpwait() {
    asm volatile("cp.async.wait_group %0;\n" :: "n"(N));
}

// ---------------- tf32 helpers --------------------------------------------
__device__ __forceinline__ u32 tf32r(float x) {
    u32 u; asm("cvt.rna.tf32.f32 %0, %1;" : "=r"(u) : "f"(x)); return u;
}
__device__ __forceinline__ void mma_tf32(float d[4], const u32 a[4], u32 b0, u32 b1) {
    asm volatile(
        "mma.sync.aligned.m16n8k8.row.col.f32.tf32.tf32.f32 "
        "{%0,%1,%2,%3}, {%4,%5,%6,%7}, {%8,%9}, {%0,%1,%2,%3};\n"
        : "+f"(d[0]), "+f"(d[1]), "+f"(d[2]), "+f"(d[3])
        : "r"(a[0]), "r"(a[1]), "r"(a[2]), "r"(a[3]), "r"(b0), "r"(b1));
}

// ---------------------------------------------------------------------------
// tf32 implicit-GEMM 3x3 conv. Block: 256 thr = 8 warps; pixel tile 8 rows x
// 16 cols; warp w owns row w (m16 = 16 pixel columns). N-sub = 32 oc (4 n8
// frags / warp). K = 9 taps x IC: per ic-chunk of 8, the halo patch gives A
// for every tap by shifted indexing. Weights pre-rounded to tf32, repacked
// [tap][k8][oc40] per chunk (stride 40 => conflict-free LDS).
// cp.async double-buffered staging (R8-proven pattern).
// ---------------------------------------------------------------------------
#define A_PLANE (10 * 20)              // padded patch plane (floats)
#define A_BYTES (8 * A_PLANE * 4)      // 6400 B per buffer
#define B_FLOATS (72 * 40)             // 2880 per chunk
#define B_BYTES (B_FLOATS * 4)         // 11520 B per buffer
#define NSTGA 6                        // ceil(8*10*18 / 256)

__global__ void __launch_bounds__(256, 2) conv_mma_kernel(
    const float* __restrict__ inA, int nA,
    const float* __restrict__ inB, int nB,
    const float* __restrict__ inC, int nC,
    const float* __restrict__ wrep,   // repacked tf32 weights
    const float* __restrict__ bias,
    float* __restrict__ out, int OC, int chunks, int zTiles, int doLrelu)
{
    const int bz = blockIdx.z;
    const int b  = bz / zTiles;
    const int zi = bz - b * zTiles;
    const int ocBase = zi * 32;

    const int tid  = threadIdx.x;
    const int lane = tid & 31;
    const int warp = tid >> 5;         // 0..7 = pixel row within tile
    const int gid  = lane >> 2;        // 0..7
    const int tig  = lane & 3;         // 0..3

    const int h0 = blockIdx.y * 8;
    const int w0 = blockIdx.x * 16;
    const int ICt = nA + nB + nC;

    __shared__ float sA[2][8][10][20]; // [buf][plane(k8)][row][col]
    __shared__ float sB[2][72][40];    // [buf][tap*8+kk][oc40]

    // ---- precompute A staging plan: 8 planes x 10 rows x 18 cols -------
    int  goff[NSTGA];
    int  ginb[NSTGA];
    u32  sofs[NSTGA];
    int  plane[NSTGA];
    int  nElems = 0;
#pragma unroll
    for (int s = 0; s < NSTGA; s++) {
        int i = tid + s * 256;
        if (i < 8 * 10 * 18) {
            int p = i / 180, rem = i - p * 180;
            int r = rem / 18, c = rem - r * 18;
            int gy = h0 + r - 1, gx = w0 + c - 1;
            ginb[s] = (gy >= 0 && gy < HH && gx >= 0 && gx < WW) ? 1 : 0;
            int gyc = min(max(gy, 0), HH - 1);
            int gxc = min(max(gx, 0), WW - 1);
            goff[s]  = gyc * WW + gxc;
            sofs[s]  = (u32)(((p * 10 + r) * 20 + c) * 4);
            plane[s] = p;
            nElems = s + 1;
        }
    }
    const u32 sAbase = s2u(&sA[0][0][0][0]);
    const u32 sBbase = s2u(&sB[0][0][0]);
    const float* wz = wrep + (size_t)zi * chunks * B_FLOATS;

    auto fetchAsync = [&](int buf, int ch) {
        // A patches (8 ic planes, zero-filled outside image / beyond ICt)
#pragma unroll
        for (int s = 0; s < NSTGA; s++) {
            if (s < nElems) {
                int ic = ch * 8 + plane[s];
                const float* base;
                if (ic < nA)            base = inA + ((size_t)(b * nA + ic)) * HW;
                else if (ic < nA + nB)  base = inB + ((size_t)(b * nB + (ic - nA))) * HW;
                else if (ic < ICt)      base = inC + ((size_t)(b * nC + (ic - nA - nB))) * HW;
                else                    base = inA;             // dummy (sz=0)
                int sz = (ic < ICt && ginb[s]) ? 4 : 0;
                cpasync4(sAbase + (u32)buf * A_BYTES + sofs[s], base + goff[s], sz);
            }
        }
        // B weights: 720 float4 granules, contiguous
        const float* wsrc = wz + (size_t)ch * B_FLOATS;
#pragma unroll
        for (int s = 0; s < 3; s++) {
            int g = tid + s * 256;
            if (g < B_FLOATS / 4)
                cpasync16(sBbase + (u32)buf * B_BYTES + (u32)g * 16, wsrc + g * 4);
        }
    };

    float acc[4][4];
#pragma unroll
    for (int t = 0; t < 4; t++)
#pragma unroll
        for (int q = 0; q < 4; q++) acc[t][q] = 0.f;

    fetchAsync(0, 0);
    cpcommit();

    int buf = 0;
    for (int ch = 0; ch < chunks; ch++) {
        if (ch + 1 < chunks) {
            fetchAsync(buf ^ 1, ch + 1);
            cpcommit();
            cpwait<1>();
        } else {
            cpwait<0>();
        }
        __syncthreads();

        const float (*PA)[10][20] = sA[buf];
        const float (*PB)[40]     = sB[buf];

#pragma unroll
        for (int tap = 0; tap < 9; tap++) {
            const int dy = tap / 3, dx = tap % 3;     // patch offsets (0..2)
            u32 a[4];
            a[0] = tf32r(PA[tig    ][warp + dy][gid     + dx]);
            a[1] = tf32r(PA[tig    ][warp + dy][gid + 8 + dx]);
            a[2] = tf32r(PA[tig + 4][warp + dy][gid     + dx]);
            a[3] = tf32r(PA[tig + 4][warp + dy][gid + 8 + dx]);
#pragma unroll
            for (int t = 0; t < 4; t++) {
                u32 b0 = __float_as_uint(PB[tap * 8 + tig    ][t * 8 + gid]);
                u32 b1 = __float_as_uint(PB[tap * 8 + tig + 4][t * 8 + gid]);
                mma_tf32(acc[t], a, b0, b1);
            }
        }

        __syncthreads();
        buf ^= 1;
    }

    // ---- epilogue: bias, lrelu, guarded stores -------------------------
    // c0:(row gid, col 2tig) c1:(row gid, col 2tig+1) c2/c3: row gid+8
    const int py  = h0 + warp;
    const int px0 = w0 + gid;
#pragma unroll
    for (int t = 0; t < 4; t++) {
        int oc = ocBase + t * 8 + 2 * tig;
#pragma unroll
        for (int e = 0; e < 2; e++) {
            int oce = oc + e;
            if (oce < OC) {
                float bv = bias[oce];
                float v0 = acc[t][e]     + bv;     // row gid
                float v1 = acc[t][e + 2] + bv;     // row gid+8
                if (doLrelu) {
                    v0 = (v0 >= 0.f) ? v0 : 0.1f * v0;
                    v1 = (v1 >= 0.f) ? v1 : 0.1f * v1;
                }
                float* dst = out + ((size_t)(b * OC + oce)) * HW + py * WW;
                dst[px0]     = v0;
                dst[px0 + 8] = v1;
            }
        }
    }
}

// ---------------------------------------------------------------------------
// Repack conv weights [oc][ic][tap] -> [z][chunk][tap][k8][oc40], tf32-rounded,
// zero-padded beyond IC / OC / oc40>=32.
// ---------------------------------------------------------------------------
__global__ void repack_convw_kernel(const float* __restrict__ w, float* __restrict__ dst,
                                    int IC, int OC, int chunks, int zTiles)
{
    int total = zTiles * chunks * B_FLOATS;
    int i = blockIdx.x * blockDim.x + threadIdx.x;
    if (i >= total) return;
    int oc40 = i % 40;
    int row  = (i / 40) % 72;        // tap*8 + kk
    int ch   = (i / (40 * 72)) % chunks;
    int z    = i / (40 * 72 * chunks);
    int kk = row & 7, tap = row >> 3;
    int ic  = ch * 8 + kk;
    int ocg = z * 32 + oc40;
    float v = 0.f;
    if (oc40 < 32 && ic < IC && ocg < OC)
        v = w[((size_t)ocg * IC + ic) * 9 + tap];
    u32 u; asm("cvt.rna.tf32.f32 %0, %1;" : "=r"(u) : "f"(v));
    dst[i] = __uint_as_float(u);
}

// ---------------------------------------------------------------------------
// Repack dcn_w [o][g*8+c][k] into g_dcnw[(g*9+k)*512 + o*8 + c].
// ---------------------------------------------------------------------------
__global__ void repack_dcnw_kernel(const float* __restrict__ w)
{
    int i = blockIdx.x * blockDim.x + threadIdx.x;
    if (i >= 8 * 9 * 512) return;
    int gk = i >> 9;
    int oc = i & 511;
    int g = gk / 9, k = gk - g * 9;
    int o = oc >> 3, c = oc & 7;
    g_dcnw[i] = w[(size_t)o * 576 + (g * 8 + c) * 9 + k];
}

// ---------------------------------------------------------------------------
// Modulated deformable conv (unchanged, fp32; proven R9 version).
// ---------------------------------------------------------------------------
__global__ void __launch_bounds__(256, 2) dcn_kernel(
    const float* __restrict__ feat,
    const float* __restrict__ om,
    const float* __restrict__ flows,
    const float* __restrict__ bias,
    float* __restrict__ out)
{
    const int b  = blockIdx.z;
    const int tx = threadIdx.x, ty = threadIdx.y;
    const int tid = ty * 16 + tx;
    const int h = blockIdx.y * 16 + ty;
    const int w = blockIdx.x * 16 + tx;
    const int pix = h * WW + w;

    __shared__ float sWg[2][9 * 512];

    const u32 sWgBase = s2u(&sWg[0][0]);
    const u32 slabBytes = 9 * 512 * 4;

    auto stageSlab = [&](int buf, int g) {
        const float* src = g_dcnw + (size_t)g * 9 * 512;
        const u32 dst = sWgBase + (u32)buf * slabBytes;
        for (int j = tid; j < 9 * 128; j += 256)
            cpasync16(dst + (u32)j * 16, src + (size_t)j * 4);
    };

    float acc[64];
#pragma unroll
    for (int o = 0; o < 64; o++) acc[o] = 0.f;

    const float flowX = flows[(b * 2 + 0) * HW + pix];
    const float flowY = flows[(b * 2 + 1) * HW + pix];
    const float* omb = om   + (size_t)b * 216 * HW;
    const float* fb  = feat + (size_t)b * 64 * HW;

    stageSlab(0, 0);
    cpcommit();

    for (int g = 0; g < 8; g++) {
        const int buf = g & 1;
        cpwait<0>();
        __syncthreads();
        if (g + 1 < 8) {
            stageSlab(buf ^ 1, g + 1);
            cpcommit();
        }

        const float* fgc = fb + (g * 8) * HW;
        const float* wslab = &sWg[buf][0];

#pragma unroll
        for (int k = 0; k < 9; k++) {
            const int kh = k / 3, kw = k - kh * 3;
            float dy = omb[(g * 18 + 2 * k + 0) * HW + pix] + flowY;
            float dx = omb[(g * 18 + 2 * k + 1) * HW + pix] + flowX;
            float mv = omb[(144 + g * 9 + k) * HW + pix];
            mv = 1.f / (1.f + __expf(-mv));

            float y = (float)h - 1.f + (float)kh + dy;
            float x = (float)w - 1.f + (float)kw + dx;
            float y0f = floorf(y), x0f = floorf(x);
            int y0 = (int)y0f, x0 = (int)x0f;
            float fy = y - y0f, fx = x - x0f;

            float w00 = (1.f - fy) * (1.f - fx);
            float w01 = (1.f - fy) * fx;
            float w10 = fy * (1.f - fx);
            float w11 = fy * fx;

            const bool iy0 = (y0 >= 0) && (y0 < HH);
            const bool iy1 = (y0 + 1 >= 0) && (y0 + 1 < HH);
            const bool ix0 = (x0 >= 0) && (x0 < WW);
            const bool ix1 = (x0 + 1 >= 0) && (x0 + 1 < WW);
            w00 = (iy0 && ix0) ? w00 * mv : 0.f;
            w01 = (iy0 && ix1) ? w01 * mv : 0.f;
            w10 = (iy1 && ix0) ? w10 * mv : 0.f;
            w11 = (iy1 && ix1) ? w11 * mv : 0.f;

            int yc0 = min(max(y0, 0), HH - 1);
            int yc1 = min(max(y0 + 1, 0), HH - 1);
            int xc0 = min(max(x0, 0), WW - 1);
            int xc1 = min(max(x0 + 1, 0), WW - 1);
            int i00 = yc0 * WW + xc0, i01 = yc0 * WW + xc1;
            int i10 = yc1 * WW + xc0, i11 = yc1 * WW + xc1;

            float val[8];
#pragma unroll
            for (int c = 0; c < 8; c++) {
                const float* fc = fgc + c * HW;
                val[c] = w00 * fc[i00] + w01 * fc[i01]
                       + w10 * fc[i10] + w11 * fc[i11];
            }

            const float4* sW4 = (const float4*)(wslab + k * 512);
#pragma unroll
            for (int o = 0; o < 64; o++) {
                float4 wa = sW4[o * 2 + 0];
                float4 wb = sW4[o * 2 + 1];
                acc[o] += val[0] * wa.x + val[1] * wa.y + val[2] * wa.z + val[3] * wa.w
                        + val[4] * wb.x + val[5] * wb.y + val[6] * wb.z + val[7] * wb.w;
            }
        }
    }

#pragma unroll
    for (int o = 0; o < 64; o++) {
        float r = acc[o] + bias[o];
        r = (r >= 0.f) ? r : 0.1f * r;
        out[((size_t)(b * 64 + o)) * HW + pix] = r;
    }
}

// ---------------------------------------------------------------------------
extern "C" void kernel_launch(void* const* d_in, const int* in_sizes, int n_in,
                              void* d_out, int out_size)
{
    const float* ref_fea2X      = (const float*)d_in[0];
    const float* ref_fea2X_flow = (const float*)d_in[1];
    const float* lr_shake_fea   = (const float*)d_in[2];
    const float* flows          = (const float*)d_in[3];
    const float* w1             = (const float*)d_in[4];
    const float* b1             = (const float*)d_in[5];
    const float* w2             = (const float*)d_in[6];
    const float* b2             = (const float*)d_in[7];
    const float* w_om           = (const float*)d_in[8];
    const float* b_om           = (const float*)d_in[9];
    const float* dcn_w          = (const float*)d_in[10];
    const float* dcn_b          = (const float*)d_in[11];
    float* out = (float*)d_out;

    float *feat1, *feat2, *omb, *wc1, *wc2, *wom;
    cudaGetSymbolAddress((void**)&feat1, g_feat1);
    cudaGetSymbolAddress((void**)&feat2, g_feat2);
    cudaGetSymbolAddress((void**)&omb,   g_om);
    cudaGetSymbolAddress((void**)&wc1,   g_wc1);
    cudaGetSymbolAddress((void**)&wc2,   g_wc2);
    cudaGetSymbolAddress((void**)&wom,   g_wom);

    // weight repacks (independent of activations)
    repack_dcnw_kernel<<<(8 * 9 * 512 + 255) / 256, 256>>>(dcn_w);
    repack_convw_kernel<<<(2 * 17 * B_FLOATS + 255) / 256, 256>>>(w1,   wc1, 130, 64, 17, 2);
    repack_convw_kernel<<<(2 * 8  * B_FLOATS + 255) / 256, 256>>>(w2,   wc2, 64,  64,  8, 2);
    repack_convw_kernel<<<(7 * 8  * B_FLOATS + 255) / 256, 256>>>(w_om, wom, 64, 216, 8, 7);

    dim3 thrM(256);
    // conv1: concat(ref_fea2X_flow, lr_shake_fea, flows) 130 -> 64, lrelu
    conv_mma_kernel<<<dim3(8, 16, BB * 2), thrM>>>(
        ref_fea2X_flow, 64, lr_shake_fea, 64, flows, 2,
        wc1, b1, feat1, 64, 17, 2, 1);
    // conv2: 64 -> 64, lrelu
    conv_mma_kernel<<<dim3(8, 16, BB * 2), thrM>>>(
        feat1, 64, (const float*)0, 0, (const float*)0, 0,
        wc2, b2, feat2, 64, 8, 2, 1);
    // conv_om: 64 -> 216, raw
    conv_mma_kernel<<<dim3(8, 16, BB * 7), thrM>>>(
        feat2, 64, (const float*)0, 0, (const float*)0, 0,
        wom, b_om, omb, 216, 8, 7, 0);

    // modulated deformable conv + lrelu (fp32)
    dcn_kernel<<<dim3(8, 8, BB), dim3(16, 16)>>>(ref_fea2X, omb, flows, dcn_b, out);
}

// round 11
// speedup vs baseline: 3.1283x; 1.0465x over previous
#include <cuda_runtime.h>
#include <math.h>

#define HH 128
#define WW 128
#define HW (HH * WW)
#define BB 2

typedef unsigned int u32;

// ---------------- scratch (static device allocations; no runtime alloc) ----
__device__ float g_feat1[BB * 64 * HW];     // after conv1+lrelu
__device__ float g_feat2[BB * 64 * HW];     // after conv2+lrelu
__device__ float g_om[BB * 216 * HW];       // raw conv_om output
__device__ float g_dcnw[8 * 9 * 512];       // dcn weights [(g*9+k)][o*8+c]
// repacked conv weights, tf32-rounded: [z][chunk][tap][k8][oc40]
__device__ float g_wc1[2 * 17 * 2880];
__device__ float g_wc2[2 * 8 * 2880];
__device__ float g_wom[7 * 8 * 2880];

// ---------------- cp.async helpers ----------------------------------------
__device__ __forceinline__ u32 s2u(const void* p) {
    return (u32)__cvta_generic_to_shared(p);
}
__device__ __forceinline__ void cpasync4(u32 dst, const void* src, int srcsize) {
    asm volatile("cp.async.ca.shared.global [%0], [%1], 4, %2;\n"
                 :: "r"(dst), "l"(src), "r"(srcsize));
}
__device__ __forceinline__ void cpasync16(u32 dst, const void* src) {
    asm volatile("cp.async.cg.shared.global [%0], [%1], 16;\n"
                 :: "r"(dst), "l"(src));
}
__device__ __forceinline__ void cpcommit() {
    asm volatile("cp.async.commit_group;\n");
}
template <int N>
__device__ __forceinline__ void cpwait() {
    asm volatile("cp.async.wait_group %0;\n" :: "n"(N));
}

// ---------------- tf32 helpers --------------------------------------------
__device__ __forceinline__ u32 tf32r(float x) {
    u32 u; asm("cvt.rna.tf32.f32 %0, %1;" : "=r"(u) : "f"(x)); return u;
}
__device__ __forceinline__ void mma_tf32(float d[4], const u32 a[4], u32 b0, u32 b1) {
    asm volatile(
        "mma.sync.aligned.m16n8k8.row.col.f32.tf32.tf32.f32 "
        "{%0,%1,%2,%3}, {%4,%5,%6,%7}, {%8,%9}, {%0,%1,%2,%3};\n"
        : "+f"(d[0]), "+f"(d[1]), "+f"(d[2]), "+f"(d[3])
        : "r"(a[0]), "r"(a[1]), "r"(a[2]), "r"(a[3]), "r"(b0), "r"(b1));
}

// ---------------------------------------------------------------------------
// tf32 implicit-GEMM 3x3 conv (proven R10 version, unchanged).
// ---------------------------------------------------------------------------
#define A_PLANE (10 * 20)
#define A_BYTES (8 * A_PLANE * 4)
#define B_FLOATS (72 * 40)
#define B_BYTES (B_FLOATS * 4)
#define NSTGA 6

__global__ void __launch_bounds__(256, 2) conv_mma_kernel(
    const float* __restrict__ inA, int nA,
    const float* __restrict__ inB, int nB,
    const float* __restrict__ inC, int nC,
    const float* __restrict__ wrep,
    const float* __restrict__ bias,
    float* __restrict__ out, int OC, int chunks, int zTiles, int doLrelu)
{
    const int bz = blockIdx.z;
    const int b  = bz / zTiles;
    const int zi = bz - b * zTiles;
    const int ocBase = zi * 32;

    const int tid  = threadIdx.x;
    const int lane = tid & 31;
    const int warp = tid >> 5;
    const int gid  = lane >> 2;
    const int tig  = lane & 3;

    const int h0 = blockIdx.y * 8;
    const int w0 = blockIdx.x * 16;
    const int ICt = nA + nB + nC;

    __shared__ float sA[2][8][10][20];
    __shared__ float sB[2][72][40];

    int  goff[NSTGA];
    int  ginb[NSTGA];
    u32  sofs[NSTGA];
    int  plane[NSTGA];
    int  nElems = 0;
#pragma unroll
    for (int s = 0; s < NSTGA; s++) {
        int i = tid + s * 256;
        if (i < 8 * 10 * 18) {
            int p = i / 180, rem = i - p * 180;
            int r = rem / 18, c = rem - r * 18;
            int gy = h0 + r - 1, gx = w0 + c - 1;
            ginb[s] = (gy >= 0 && gy < HH && gx >= 0 && gx < WW) ? 1 : 0;
            int gyc = min(max(gy, 0), HH - 1);
            int gxc = min(max(gx, 0), WW - 1);
            goff[s]  = gyc * WW + gxc;
            sofs[s]  = (u32)(((p * 10 + r) * 20 + c) * 4);
            plane[s] = p;
            nElems = s + 1;
        }
    }
    const u32 sAbase = s2u(&sA[0][0][0][0]);
    const u32 sBbase = s2u(&sB[0][0][0]);
    const float* wz = wrep + (size_t)zi * chunks * B_FLOATS;

    auto fetchAsync = [&](int buf, int ch) {
#pragma unroll
        for (int s = 0; s < NSTGA; s++) {
            if (s < nElems) {
                int ic = ch * 8 + plane[s];
                const float* base;
                if (ic < nA)            base = inA + ((size_t)(b * nA + ic)) * HW;
                else if (ic < nA + nB)  base = inB + ((size_t)(b * nB + (ic - nA))) * HW;
                else if (ic < ICt)      base = inC + ((size_t)(b * nC + (ic - nA - nB))) * HW;
                else                    base = inA;
                int sz = (ic < ICt && ginb[s]) ? 4 : 0;
                cpasync4(sAbase + (u32)buf * A_BYTES + sofs[s], base + goff[s], sz);
            }
        }
        const float* wsrc = wz + (size_t)ch * B_FLOATS;
#pragma unroll
        for (int s = 0; s < 3; s++) {
            int g = tid + s * 256;
            if (g < B_FLOATS / 4)
                cpasync16(sBbase + (u32)buf * B_BYTES + (u32)g * 16, wsrc + g * 4);
        }
    };

    float acc[4][4];
#pragma unroll
    for (int t = 0; t < 4; t++)
#pragma unroll
        for (int q = 0; q < 4; q++) acc[t][q] = 0.f;

    fetchAsync(0, 0);
    cpcommit();

    int buf = 0;
    for (int ch = 0; ch < chunks; ch++) {
        if (ch + 1 < chunks) {
            fetchAsync(buf ^ 1, ch + 1);
            cpcommit();
            cpwait<1>();
        } else {
            cpwait<0>();
        }
        __syncthreads();

        const float (*PA)[10][20] = sA[buf];
        const float (*PB)[40]     = sB[buf];

#pragma unroll
        for (int tap = 0; tap < 9; tap++) {
            const int dy = tap / 3, dx = tap % 3;
            u32 a[4];
            a[0] = tf32r(PA[tig    ][warp + dy][gid     + dx]);
            a[1] = tf32r(PA[tig    ][warp + dy][gid + 8 + dx]);
            a[2] = tf32r(PA[tig + 4][warp + dy][gid     + dx]);
            a[3] = tf32r(PA[tig + 4][warp + dy][gid + 8 + dx]);
#pragma unroll
            for (int t = 0; t < 4; t++) {
                u32 b0 = __float_as_uint(PB[tap * 8 + tig    ][t * 8 + gid]);
                u32 b1 = __float_as_uint(PB[tap * 8 + tig + 4][t * 8 + gid]);
                mma_tf32(acc[t], a, b0, b1);
            }
        }

        __syncthreads();
        buf ^= 1;
    }

    const int py  = h0 + warp;
    const int px0 = w0 + gid;
#pragma unroll
    for (int t = 0; t < 4; t++) {
        int oc = ocBase + t * 8 + 2 * tig;
#pragma unroll
        for (int e = 0; e < 2; e++) {
            int oce = oc + e;
            if (oce < OC) {
                float bv = bias[oce];
                float v0 = acc[t][e]     + bv;
                float v1 = acc[t][e + 2] + bv;
                if (doLrelu) {
                    v0 = (v0 >= 0.f) ? v0 : 0.1f * v0;
                    v1 = (v1 >= 0.f) ? v1 : 0.1f * v1;
                }
                float* dst = out + ((size_t)(b * OC + oce)) * HW + py * WW;
                dst[px0]     = v0;
                dst[px0 + 8] = v1;
            }
        }
    }
}

// ---------------------------------------------------------------------------
// Repack conv weights -> [z][chunk][tap][k8][oc40], tf32-rounded.
// ---------------------------------------------------------------------------
__global__ void repack_convw_kernel(const float* __restrict__ w, float* __restrict__ dst,
                                    int IC, int OC, int chunks, int zTiles)
{
    int total = zTiles * chunks * B_FLOATS;
    int i = blockIdx.x * blockDim.x + threadIdx.x;
    if (i >= total) return;
    int oc40 = i % 40;
    int row  = (i / 40) % 72;
    int ch   = (i / (40 * 72)) % chunks;
    int z    = i / (40 * 72 * chunks);
    int kk = row & 7, tap = row >> 3;
    int ic  = ch * 8 + kk;
    int ocg = z * 32 + oc40;
    float v = 0.f;
    if (oc40 < 32 && ic < IC && ocg < OC)
        v = w[((size_t)ocg * IC + ic) * 9 + tap];
    u32 u; asm("cvt.rna.tf32.f32 %0, %1;" : "=r"(u) : "f"(v));
    dst[i] = __uint_as_float(u);
}

// ---------------------------------------------------------------------------
// Repack dcn_w [o][g*8+c][k] into g_dcnw[(g*9+k)*512 + o*8 + c].
// ---------------------------------------------------------------------------
__global__ void repack_dcnw_kernel(const float* __restrict__ w)
{
    int i = blockIdx.x * blockDim.x + threadIdx.x;
    if (i >= 8 * 9 * 512) return;
    int gk = i >> 9;
    int oc = i & 511;
    int g = gk / 9, k = gk - g * 9;
    int o = oc >> 3, c = oc & 7;
    g_dcnw[i] = w[(size_t)o * 576 + (g * 8 + c) * 9 + k];
}

// ---------------------------------------------------------------------------
// Modulated deformable conv, fp32. R10 arithmetic, reshaped for occupancy:
// 128-thread blocks (16x8 pixel tile) -> 256 CTAs (~2/SM) so scattered
// bilinear-gather latency is covered. om values for the whole group are
// batch-loaded (MLP 27) before the k loop.
// ---------------------------------------------------------------------------
__global__ void __launch_bounds__(128, 3) dcn_kernel(
    const float* __restrict__ feat,
    const float* __restrict__ om,
    const float* __restrict__ flows,
    const float* __restrict__ bias,
    float* __restrict__ out)
{
    const int b  = blockIdx.z;
    const int tx = threadIdx.x;            // 0..15
    const int ty = threadIdx.y;            // 0..7
    const int tid = ty * 16 + tx;          // 0..127
    const int h = blockIdx.y * 8 + ty;
    const int w = blockIdx.x * 16 + tx;
    const int pix = h * WW + w;

    __shared__ float sWg[2][9 * 512];

    const u32 sWgBase = s2u(&sWg[0][0]);
    const u32 slabBytes = 9 * 512 * 4;

    auto stageSlab = [&](int buf, int g) {
        const float* src = g_dcnw + (size_t)g * 9 * 512;
        const u32 dst = sWgBase + (u32)buf * slabBytes;
        for (int j = tid; j < 9 * 128; j += 128)
            cpasync16(dst + (u32)j * 16, src + (size_t)j * 4);
    };

    float acc[64];
#pragma unroll
    for (int o = 0; o < 64; o++) acc[o] = 0.f;

    const float flowX = flows[(b * 2 + 0) * HW + pix];
    const float flowY = flows[(b * 2 + 1) * HW + pix];
    const float* omb = om   + (size_t)b * 216 * HW;
    const float* fb  = feat + (size_t)b * 64 * HW;

    stageSlab(0, 0);
    cpcommit();

    for (int g = 0; g < 8; g++) {
        const int buf = g & 1;
        cpwait<0>();
        __syncthreads();
        if (g + 1 < 8) {
            stageSlab(buf ^ 1, g + 1);
            cpcommit();
        }

        // batch-load this group's om values (high MLP, coalesced)
        float offv[18], mskv[9];
#pragma unroll
        for (int q = 0; q < 18; q++)
            offv[q] = omb[((size_t)(g * 18 + q)) * HW + pix];
#pragma unroll
        for (int q = 0; q < 9; q++)
            mskv[q] = omb[((size_t)(144 + g * 9 + q)) * HW + pix];

        const float* fgc = fb + (g * 8) * HW;
        const float* wslab = &sWg[buf][0];

#pragma unroll
        for (int k = 0; k < 9; k++) {
            const int kh = k / 3, kw = k - kh * 3;
            float dy = offv[2 * k + 0] + flowY;
            float dx = offv[2 * k + 1] + flowX;
            float mv = mskv[k];
            mv = 1.f / (1.f + __expf(-mv));

            float y = (float)h - 1.f + (float)kh + dy;
            float x = (float)w - 1.f + (float)kw + dx;
            float y0f = floorf(y), x0f = floorf(x);
            int y0 = (int)y0f, x0 = (int)x0f;
            float fy = y - y0f, fx = x - x0f;

            float w00 = (1.f - fy) * (1.f - fx);
            float w01 = (1.f - fy) * fx;
            float w10 = fy * (1.f - fx);
            float w11 = fy * fx;

            const bool iy0 = (y0 >= 0) && (y0 < HH);
            const bool iy1 = (y0 + 1 >= 0) && (y0 + 1 < HH);
            const bool ix0 = (x0 >= 0) && (x0 < WW);
            const bool ix1 = (x0 + 1 >= 0) && (x0 + 1 < WW);
            w00 = (iy0 && ix0) ? w00 * mv : 0.f;
            w01 = (iy0 && ix1) ? w01 * mv : 0.f;
            w10 = (iy1 && ix0) ? w10 * mv : 0.f;
            w11 = (iy1 && ix1) ? w11 * mv : 0.f;

            int yc0 = min(max(y0, 0), HH - 1);
            int yc1 = min(max(y0 + 1, 0), HH - 1);
            int xc0 = min(max(x0, 0), WW - 1);
            int xc1 = min(max(x0 + 1, 0), WW - 1);
            int i00 = yc0 * WW + xc0, i01 = yc0 * WW + xc1;
            int i10 = yc1 * WW + xc0, i11 = yc1 * WW + xc1;

            float val[8];
#pragma unroll
            for (int c = 0; c < 8; c++) {
                const float* fc = fgc + c * HW;
                val[c] = w00 * fc[i00] + w01 * fc[i01]
                       + w10 * fc[i10] + w11 * fc[i11];
            }

            const float4* sW4 = (const float4*)(wslab + k * 512);
#pragma unroll
            for (int o = 0; o < 64; o++) {
                float4 wa = sW4[o * 2 + 0];
                float4 wb = sW4[o * 2 + 1];
                acc[o] += val[0] * wa.x + val[1] * wa.y + val[2] * wa.z + val[3] * wa.w
                        + val[4] * wb.x + val[5] * wb.y + val[6] * wb.z + val[7] * wb.w;
            }
        }
    }

#pragma unroll
    for (int o = 0; o < 64; o++) {
        float r = acc[o] + bias[o];
        r = (r >= 0.f) ? r : 0.1f * r;
        out[((size_t)(b * 64 + o)) * HW + pix] = r;
    }
}

// ---------------------------------------------------------------------------
extern "C" void kernel_launch(void* const* d_in, const int* in_sizes, int n_in,
                              void* d_out, int out_size)
{
    const float* ref_fea2X      = (const float*)d_in[0];
    const float* ref_fea2X_flow = (const float*)d_in[1];
    const float* lr_shake_fea   = (const float*)d_in[2];
    const float* flows          = (const float*)d_in[3];
    const float* w1             = (const float*)d_in[4];
    const float* b1             = (const float*)d_in[5];
    const float* w2             = (const float*)d_in[6];
    const float* b2             = (const float*)d_in[7];
    const float* w_om           = (const float*)d_in[8];
    const float* b_om           = (const float*)d_in[9];
    const float* dcn_w          = (const float*)d_in[10];
    const float* dcn_b          = (const float*)d_in[11];
    float* out = (float*)d_out;

    float *feat1, *feat2, *omb, *wc1, *wc2, *wom;
    cudaGetSymbolAddress((void**)&feat1, g_feat1);
    cudaGetSymbolAddress((void**)&feat2, g_feat2);
    cudaGetSymbolAddress((void**)&omb,   g_om);
    cudaGetSymbolAddress((void**)&wc1,   g_wc1);
    cudaGetSymbolAddress((void**)&wc2,   g_wc2);
    cudaGetSymbolAddress((void**)&wom,   g_wom);

    // weight repacks (independent of activations)
    repack_dcnw_kernel<<<(8 * 9 * 512 + 255) / 256, 256>>>(dcn_w);
    repack_convw_kernel<<<(2 * 17 * B_FLOATS + 255) / 256, 256>>>(w1,   wc1, 130, 64, 17, 2);
    repack_convw_kernel<<<(2 * 8  * B_FLOATS + 255) / 256, 256>>>(w2,   wc2, 64,  64,  8, 2);
    repack_convw_kernel<<<(7 * 8  * B_FLOATS + 255) / 256, 256>>>(w_om, wom, 64, 216, 8, 7);

    dim3 thrM(256);
    // conv1: concat(ref_fea2X_flow, lr_shake_fea, flows) 130 -> 64, lrelu
    conv_mma_kernel<<<dim3(8, 16, BB * 2), thrM>>>(
        ref_fea2X_flow, 64, lr_shake_fea, 64, flows, 2,
        wc1, b1, feat1, 64, 17, 2, 1);
    // conv2: 64 -> 64, lrelu
    conv_mma_kernel<<<dim3(8, 16, BB * 2), thrM>>>(
        feat1, 64, (const float*)0, 0, (const float*)0, 0,
        wc2, b2, feat2, 64, 8, 2, 1);
    // conv_om: 64 -> 216, raw
    conv_mma_kernel<<<dim3(8, 16, BB * 7), thrM>>>(
        feat2, 64, (const float*)0, 0, (const float*)0, 0,
        wom, b_om, omb, 216, 8, 7, 0);

    // modulated deformable conv + lrelu (fp32, 256 CTAs)
    dcn_kernel<<<dim3(8, 16, BB), dim3(16, 8)>>>(ref_fea2X, omb, flows, dcn_b, out);
}

// round 12
// speedup vs baseline: 4.1707x; 1.3332x over previous
#include <cuda_runtime.h>
#include <math.h>

#define HH 128
#define WW 128
#define HW (HH * WW)
#define BB 2

typedef unsigned int u32;

// ---------------- scratch (static device allocations; no runtime alloc) ----
__device__ float g_feat1[BB * 64 * HW];     // after conv1+lrelu
__device__ float g_feat2[BB * 64 * HW];     // after conv2+lrelu
__device__ float g_om[BB * 216 * HW];       // raw conv_om output
__device__ float g_dcnwB[8 * 9 * 8 * 32 * 2]; // dcn weights in MMA B-frag order
// repacked conv weights, tf32-rounded: [z][chunk][tap][k8][oc40]
__device__ float g_wc1[2 * 17 * 2880];
__device__ float g_wc2[2 * 8 * 2880];
__device__ float g_wom[7 * 8 * 2880];

// ---------------- cp.async helpers ----------------------------------------
__device__ __forceinline__ u32 s2u(const void* p) {
    return (u32)__cvta_generic_to_shared(p);
}
__device__ __forceinline__ void cpasync4(u32 dst, const void* src, int srcsize) {
    asm volatile("cp.async.ca.shared.global [%0], [%1], 4, %2;\n"
                 :: "r"(dst), "l"(src), "r"(srcsize));
}
__device__ __forceinline__ void cpasync16(u32 dst, const void* src) {
    asm volatile("cp.async.cg.shared.global [%0], [%1], 16;\n"
                 :: "r"(dst), "l"(src));
}
__device__ __forceinline__ void cpcommit() {
    asm volatile("cp.async.commit_group;\n");
}
template <int N>
__device__ __forceinline__ void cpwait() {
    asm volatile("cp.async.wait_group %0;\n" :: "n"(N));
}

// ---------------- tf32 helpers --------------------------------------------
__device__ __forceinline__ u32 tf32r(float x) {
    u32 u; asm("cvt.rna.tf32.f32 %0, %1;" : "=r"(u) : "f"(x)); return u;
}
__device__ __forceinline__ void mma_tf32(float d[4], const u32 a[4], u32 b0, u32 b1) {
    asm volatile(
        "mma.sync.aligned.m16n8k8.row.col.f32.tf32.tf32.f32 "
        "{%0,%1,%2,%3}, {%4,%5,%6,%7}, {%8,%9}, {%0,%1,%2,%3};\n"
        : "+f"(d[0]), "+f"(d[1]), "+f"(d[2]), "+f"(d[3])
        : "r"(a[0]), "r"(a[1]), "r"(a[2]), "r"(a[3]), "r"(b0), "r"(b1));
}

// ---------------------------------------------------------------------------
// tf32 implicit-GEMM 3x3 conv (proven R10 version, unchanged).
// ---------------------------------------------------------------------------
#define A_PLANE (10 * 20)
#define A_BYTES (8 * A_PLANE * 4)
#define B_FLOATS (72 * 40)
#define B_BYTES (B_FLOATS * 4)
#define NSTGA 6

__global__ void __launch_bounds__(256, 2) conv_mma_kernel(
    const float* __restrict__ inA, int nA,
    const float* __restrict__ inB, int nB,
    const float* __restrict__ inC, int nC,
    const float* __restrict__ wrep,
    const float* __restrict__ bias,
    float* __restrict__ out, int OC, int chunks, int zTiles, int doLrelu)
{
    const int bz = blockIdx.z;
    const int b  = bz / zTiles;
    const int zi = bz - b * zTiles;
    const int ocBase = zi * 32;

    const int tid  = threadIdx.x;
    const int lane = tid & 31;
    const int warp = tid >> 5;
    const int gid  = lane >> 2;
    const int tig  = lane & 3;

    const int h0 = blockIdx.y * 8;
    const int w0 = blockIdx.x * 16;
    const int ICt = nA + nB + nC;

    __shared__ float sA[2][8][10][20];
    __shared__ float sB[2][72][40];

    int  goff[NSTGA];
    int  ginb[NSTGA];
    u32  sofs[NSTGA];
    int  plane[NSTGA];
    int  nElems = 0;
#pragma unroll
    for (int s = 0; s < NSTGA; s++) {
        int i = tid + s * 256;
        if (i < 8 * 10 * 18) {
            int p = i / 180, rem = i - p * 180;
            int r = rem / 18, c = rem - r * 18;
            int gy = h0 + r - 1, gx = w0 + c - 1;
            ginb[s] = (gy >= 0 && gy < HH && gx >= 0 && gx < WW) ? 1 : 0;
            int gyc = min(max(gy, 0), HH - 1);
            int gxc = min(max(gx, 0), WW - 1);
            goff[s]  = gyc * WW + gxc;
            sofs[s]  = (u32)(((p * 10 + r) * 20 + c) * 4);
            plane[s] = p;
            nElems = s + 1;
        }
    }
    const u32 sAbase = s2u(&sA[0][0][0][0]);
    const u32 sBbase = s2u(&sB[0][0][0]);
    const float* wz = wrep + (size_t)zi * chunks * B_FLOATS;

    auto fetchAsync = [&](int buf, int ch) {
#pragma unroll
        for (int s = 0; s < NSTGA; s++) {
            if (s < nElems) {
                int ic = ch * 8 + plane[s];
                const float* base;
                if (ic < nA)            base = inA + ((size_t)(b * nA + ic)) * HW;
                else if (ic < nA + nB)  base = inB + ((size_t)(b * nB + (ic - nA))) * HW;
                else if (ic < ICt)      base = inC + ((size_t)(b * nC + (ic - nA - nB))) * HW;
                else                    base = inA;
                int sz = (ic < ICt && ginb[s]) ? 4 : 0;
                cpasync4(sAbase + (u32)buf * A_BYTES + sofs[s], base + goff[s], sz);
            }
        }
        const float* wsrc = wz + (size_t)ch * B_FLOATS;
#pragma unroll
        for (int s = 0; s < 3; s++) {
            int g = tid + s * 256;
            if (g < B_FLOATS / 4)
                cpasync16(sBbase + (u32)buf * B_BYTES + (u32)g * 16, wsrc + g * 4);
        }
    };

    float acc[4][4];
#pragma unroll
    for (int t = 0; t < 4; t++)
#pragma unroll
        for (int q = 0; q < 4; q++) acc[t][q] = 0.f;

    fetchAsync(0, 0);
    cpcommit();

    int buf = 0;
    for (int ch = 0; ch < chunks; ch++) {
        if (ch + 1 < chunks) {
            fetchAsync(buf ^ 1, ch + 1);
            cpcommit();
            cpwait<1>();
        } else {
            cpwait<0>();
        }
        __syncthreads();

        const float (*PA)[10][20] = sA[buf];
        const float (*PB)[40]     = sB[buf];

#pragma unroll
        for (int tap = 0; tap < 9; tap++) {
            const int dy = tap / 3, dx = tap % 3;
            u32 a[4];
            a[0] = tf32r(PA[tig    ][warp + dy][gid     + dx]);
            a[1] = tf32r(PA[tig    ][warp + dy][gid + 8 + dx]);
            a[2] = tf32r(PA[tig + 4][warp + dy][gid     + dx]);
            a[3] = tf32r(PA[tig + 4][warp + dy][gid + 8 + dx]);
#pragma unroll
            for (int t = 0; t < 4; t++) {
                u32 b0 = __float_as_uint(PB[tap * 8 + tig    ][t * 8 + gid]);
                u32 b1 = __float_as_uint(PB[tap * 8 + tig + 4][t * 8 + gid]);
                mma_tf32(acc[t], a, b0, b1);
            }
        }

        __syncthreads();
        buf ^= 1;
    }

    const int py  = h0 + warp;
    const int px0 = w0 + gid;
#pragma unroll
    for (int t = 0; t < 4; t++) {
        int oc = ocBase + t * 8 + 2 * tig;
#pragma unroll
        for (int e = 0; e < 2; e++) {
            int oce = oc + e;
            if (oce < OC) {
                float bv = bias[oce];
                float v0 = acc[t][e]     + bv;
                float v1 = acc[t][e + 2] + bv;
                if (doLrelu) {
                    v0 = (v0 >= 0.f) ? v0 : 0.1f * v0;
                    v1 = (v1 >= 0.f) ? v1 : 0.1f * v1;
                }
                float* dst = out + ((size_t)(b * OC + oce)) * HW + py * WW;
                dst[px0]     = v0;
                dst[px0 + 8] = v1;
            }
        }
    }
}

// ---------------------------------------------------------------------------
// Repack conv weights -> [z][chunk][tap][k8][oc40], tf32-rounded.
// ---------------------------------------------------------------------------
__global__ void repack_convw_kernel(const float* __restrict__ w, float* __restrict__ dst,
                                    int IC, int OC, int chunks, int zTiles)
{
    int total = zTiles * chunks * B_FLOATS;
    int i = blockIdx.x * blockDim.x + threadIdx.x;
    if (i >= total) return;
    int oc40 = i % 40;
    int row  = (i / 40) % 72;
    int ch   = (i / (40 * 72)) % chunks;
    int z    = i / (40 * 72 * chunks);
    int kk = row & 7, tap = row >> 3;
    int ic  = ch * 8 + kk;
    int ocg = z * 32 + oc40;
    float v = 0.f;
    if (oc40 < 32 && ic < IC && ocg < OC)
        v = w[((size_t)ocg * IC + ic) * 9 + tap];
    u32 u; asm("cvt.rna.tf32.f32 %0, %1;" : "=r"(u) : "f"(v));
    dst[i] = __uint_as_float(u);
}

// ---------------------------------------------------------------------------
// Repack dcn_w [o][g*8+c][k] into per-lane MMA B-fragment order:
// g_dcnwB[(((g*9+k)*8 + nt)*32 + lane)*2 + pair]
//   pair 0: B[c = lane&3    ][oc = nt*8 + lane>>2]
//   pair 1: B[c = (lane&3)+4][oc = nt*8 + lane>>2]
// tf32-rounded at repack time.
// ---------------------------------------------------------------------------
__global__ void repack_dcnwB_kernel(const float* __restrict__ w)
{
    int i = blockIdx.x * blockDim.x + threadIdx.x;
    if (i >= 8 * 9 * 8 * 32 * 2) return;
    int pair = i & 1;
    int t    = i >> 1;
    int lane = t & 31;  t >>= 5;
    int nt   = t & 7;   t >>= 3;
    int k    = t % 9;
    int g    = t / 9;
    int c  = (lane & 3) + 4 * pair;
    int oc = nt * 8 + (lane >> 2);
    float v = w[(size_t)oc * 576 + (g * 8 + c) * 9 + k];
    u32 u; asm("cvt.rna.tf32.f32 %0, %1;" : "=r"(u) : "f"(v));
    g_dcnwB[i] = __uint_as_float(u);
}

// ---------------------------------------------------------------------------
// Modulated deformable conv with tf32 MMA accumulate.
// 128 threads / 4 warps; 128-pixel tile (16x8). Each warp owns its 32 px
// (2 m16 tiles); bilinear vals gathered in fp32, tf32-rounded into a
// per-warp smem slab (syncwarp only); B frags read from global (L1-hot).
// ---------------------------------------------------------------------------
__global__ void __launch_bounds__(128, 2) dcn_mma_kernel(
    const float* __restrict__ feat,
    const float* __restrict__ om,
    const float* __restrict__ flows,
    const float* __restrict__ bias,
    float* __restrict__ out)
{
    const int b  = blockIdx.z;
    const int tx = threadIdx.x;            // 0..15
    const int ty = threadIdx.y;            // 0..7
    const int tid = ty * 16 + tx;          // 0..127 (local pixel id)
    const int lane = tid & 31;
    const int warpid = tid >> 5;           // 0..3
    const int gid = lane >> 2;             // 0..7
    const int tig = lane & 3;              // 0..3
    const int h = blockIdx.y * 8 + ty;
    const int w = blockIdx.x * 16 + tx;
    const int pix = h * WW + w;

    __shared__ float sVal[4][9][32][9];    // [warp][tap][px32][c(+pad)]

    float acc[2][8][4];                    // [mtile][ntile][frag]
#pragma unroll
    for (int m = 0; m < 2; m++)
#pragma unroll
        for (int n = 0; n < 8; n++)
#pragma unroll
            for (int q = 0; q < 4; q++) acc[m][n][q] = 0.f;

    const float flowX = flows[(b * 2 + 0) * HW + pix];
    const float flowY = flows[(b * 2 + 1) * HW + pix];
    const float* omb = om   + (size_t)b * 216 * HW;
    const float* fb  = feat + (size_t)b * 64 * HW;

    for (int g = 0; g < 8; g++) {
        // ---- batch om loads (coalesced, high MLP) ----
        float offv[18], mskv[9];
#pragma unroll
        for (int q = 0; q < 18; q++)
            offv[q] = omb[((size_t)(g * 18 + q)) * HW + pix];
#pragma unroll
        for (int q = 0; q < 9; q++)
            mskv[q] = omb[((size_t)(144 + g * 9 + q)) * HW + pix];

        const float* fgc = fb + (g * 8) * HW;

        // ---- gather phase: fill this warp's val slab ----
#pragma unroll
        for (int k = 0; k < 9; k++) {
            const int kh = k / 3, kw = k - kh * 3;
            float dy = offv[2 * k + 0] + flowY;
            float dx = offv[2 * k + 1] + flowX;
            float mv = mskv[k];
            mv = 1.f / (1.f + __expf(-mv));

            float y = (float)h - 1.f + (float)kh + dy;
            float x = (float)w - 1.f + (float)kw + dx;
            float y0f = floorf(y), x0f = floorf(x);
            int y0 = (int)y0f, x0 = (int)x0f;
            float fy = y - y0f, fx = x - x0f;

            float w00 = (1.f - fy) * (1.f - fx);
            float w01 = (1.f - fy) * fx;
            float w10 = fy * (1.f - fx);
            float w11 = fy * fx;

            const bool iy0 = (y0 >= 0) && (y0 < HH);
            const bool iy1 = (y0 + 1 >= 0) && (y0 + 1 < HH);
            const bool ix0 = (x0 >= 0) && (x0 < WW);
            const bool ix1 = (x0 + 1 >= 0) && (x0 + 1 < WW);
            w00 = (iy0 && ix0) ? w00 * mv : 0.f;
            w01 = (iy0 && ix1) ? w01 * mv : 0.f;
            w10 = (iy1 && ix0) ? w10 * mv : 0.f;
            w11 = (iy1 && ix1) ? w11 * mv : 0.f;

            int yc0 = min(max(y0, 0), HH - 1);
            int yc1 = min(max(y0 + 1, 0), HH - 1);
            int xc0 = min(max(x0, 0), WW - 1);
            int xc1 = min(max(x0 + 1, 0), WW - 1);
            int i00 = yc0 * WW + xc0, i01 = yc0 * WW + xc1;
            int i10 = yc1 * WW + xc0, i11 = yc1 * WW + xc1;

#pragma unroll
            for (int c = 0; c < 8; c++) {
                const float* fc = fgc + c * HW;
                float val = w00 * fc[i00] + w01 * fc[i01]
                          + w10 * fc[i10] + w11 * fc[i11];
                sVal[warpid][k][lane][c] = __uint_as_float(tf32r(val));
            }
        }
        __syncwarp();

        // ---- MMA phase: this warp's 2 m16 tiles x 8 n8 tiles x 9 k8 ----
        const float* fragBase = g_dcnwB + (size_t)g * 9 * 8 * 64;
#pragma unroll
        for (int k = 0; k < 9; k++) {
            const float (*V)[9] = sVal[warpid][k];
            u32 a0[4], a1[4];
            a0[0] = __float_as_uint(V[gid     ][tig    ]);
            a0[1] = __float_as_uint(V[gid + 8 ][tig    ]);
            a0[2] = __float_as_uint(V[gid     ][tig + 4]);
            a0[3] = __float_as_uint(V[gid + 8 ][tig + 4]);
            a1[0] = __float_as_uint(V[gid + 16][tig    ]);
            a1[1] = __float_as_uint(V[gid + 24][tig    ]);
            a1[2] = __float_as_uint(V[gid + 16][tig + 4]);
            a1[3] = __float_as_uint(V[gid + 24][tig + 4]);
#pragma unroll
            for (int nt = 0; nt < 8; nt++) {
                float2 bb = *(const float2*)&fragBase[((k * 8 + nt) * 32 + lane) * 2];
                u32 b0 = __float_as_uint(bb.x);
                u32 b1 = __float_as_uint(bb.y);
                mma_tf32(acc[0][nt], a0, b0, b1);
                mma_tf32(acc[1][nt], a1, b0, b1);
            }
        }
        __syncwarp();   // slab reads done before next g overwrites
    }

    // ---- epilogue: bias, lrelu, scattered stores ----
    const int h0 = blockIdx.y * 8;
    const int w0 = blockIdx.x * 16;
#pragma unroll
    for (int m = 0; m < 2; m++) {
        int r0 = warpid * 32 + m * 16 + gid;   // local px rows
        int r1 = r0 + 8;
        int hA = h0 + (r0 >> 4), wA = w0 + (r0 & 15);
        int hB = h0 + (r1 >> 4), wB2 = w0 + (r1 & 15);
#pragma unroll
        for (int nt = 0; nt < 8; nt++) {
            int oc0 = nt * 8 + 2 * tig;
#pragma unroll
            for (int e = 0; e < 2; e++) {
                int oc = oc0 + e;
                float bv = bias[oc];
                float vA = acc[m][nt][e]     + bv;
                float vB = acc[m][nt][e + 2] + bv;
                vA = (vA >= 0.f) ? vA : 0.1f * vA;
                vB = (vB >= 0.f) ? vB : 0.1f * vB;
                out[((size_t)(b * 64 + oc)) * HW + hA * WW + wA]  = vA;
                out[((size_t)(b * 64 + oc)) * HW + hB * WW + wB2] = vB;
            }
        }
    }
}

// ---------------------------------------------------------------------------
extern "C" void kernel_launch(void* const* d_in, const int* in_sizes, int n_in,
                              void* d_out, int out_size)
{
    const float* ref_fea2X      = (const float*)d_in[0];
    const float* ref_fea2X_flow = (const float*)d_in[1];
    const float* lr_shake_fea   = (const float*)d_in[2];
    const float* flows          = (const float*)d_in[3];
    const float* w1             = (const float*)d_in[4];
    const float* b1             = (const float*)d_in[5];
    const float* w2             = (const float*)d_in[6];
    const float* b2             = (const float*)d_in[7];
    const float* w_om           = (const float*)d_in[8];
    const float* b_om           = (const float*)d_in[9];
    const float* dcn_w          = (const float*)d_in[10];
    const float* dcn_b          = (const float*)d_in[11];
    float* out = (float*)d_out;

    float *feat1, *feat2, *omb, *wc1, *wc2, *wom;
    cudaGetSymbolAddress((void**)&feat1, g_feat1);
    cudaGetSymbolAddress((void**)&feat2, g_feat2);
    cudaGetSymbolAddress((void**)&omb,   g_om);
    cudaGetSymbolAddress((void**)&wc1,   g_wc1);
    cudaGetSymbolAddress((void**)&wc2,   g_wc2);
    cudaGetSymbolAddress((void**)&wom,   g_wom);

    // weight repacks (independent of activations)
    repack_dcnwB_kernel<<<(8 * 9 * 8 * 32 * 2 + 255) / 256, 256>>>(dcn_w);
    repack_convw_kernel<<<(2 * 17 * B_FLOATS + 255) / 256, 256>>>(w1,   wc1, 130, 64, 17, 2);
    repack_convw_kernel<<<(2 * 8  * B_FLOATS + 255) / 256, 256>>>(w2,   wc2, 64,  64,  8, 2);
    repack_convw_kernel<<<(7 * 8  * B_FLOATS + 255) / 256, 256>>>(w_om, wom, 64, 216, 8, 7);

    dim3 thrM(256);
    // conv1: concat(ref_fea2X_flow, lr_shake_fea, flows) 130 -> 64, lrelu
    conv_mma_kernel<<<dim3(8, 16, BB * 2), thrM>>>(
        ref_fea2X_flow, 64, lr_shake_fea, 64, flows, 2,
        wc1, b1, feat1, 64, 17, 2, 1);
    // conv2: 64 -> 64, lrelu
    conv_mma_kernel<<<dim3(8, 16, BB * 2), thrM>>>(
        feat1, 64, (const float*)0, 0, (const float*)0, 0,
        wc2, b2, feat2, 64, 8, 2, 1);
    // conv_om: 64 -> 216, raw
    conv_mma_kernel<<<dim3(8, 16, BB * 7), thrM>>>(
        feat2, 64, (const float*)0, 0, (const float*)0, 0,
        wom, b_om, omb, 216, 8, 7, 0);

    // modulated deformable conv + lrelu (tf32 MMA accumulate)
    dcn_mma_kernel<<<dim3(8, 16, BB), dim3(16, 8)>>>(ref_fea2X, omb, flows, dcn_b, out);
}